// round 3
// baseline (speedup 1.0000x reference)
#include <cuda_runtime.h>
#include <cstdint>

#define N_PIX 4096
#define BATCH 4
#define CDIM  64
#define CQKD  8
#define TQ    64
#define TK    64
#define LOG2E 1.4426950408889634f

// p_s column swizzle: rows have stride 64 (16B-aligned float4s); XOR the
// 4-column group by (row>>3)&7 so the transposed-P store spreads across banks.
#define PSWZ(row, col) ((col) ^ ((((row) >> 3) & 7) << 2))

// Scratch for q, k, v (device globals: no allocation allowed)
__device__ float g_q[BATCH * CQKD * N_PIX];
__device__ float g_k[BATCH * CQKD * N_PIX];
__device__ float g_v[BATCH * CDIM * N_PIX];

// ---------- packed f32x2 helpers (Blackwell) ----------
__device__ __forceinline__ unsigned long long ffma2(unsigned long long a,
                                                    unsigned long long b,
                                                    unsigned long long c) {
    unsigned long long d;
    asm("fma.rn.f32x2 %0, %1, %2, %3;" : "=l"(d) : "l"(a), "l"(b), "l"(c));
    return d;
}
__device__ __forceinline__ unsigned long long fmul2(unsigned long long a,
                                                    unsigned long long b) {
    unsigned long long d;
    asm("mul.rn.f32x2 %0, %1, %2;" : "=l"(d) : "l"(a), "l"(b));
    return d;
}
__device__ __forceinline__ unsigned long long packf2(float lo, float hi) {
    unsigned long long r;
    asm("mov.b64 %0, {%1, %2};" : "=l"(r) : "f"(lo), "f"(hi));
    return r;
}
__device__ __forceinline__ float2 unpackf2(unsigned long long v) {
    float lo, hi;
    asm("mov.b64 {%0, %1}, %2;" : "=f"(lo), "=f"(hi) : "l"(v));
    return make_float2(lo, hi);
}
__device__ __forceinline__ float ex2(float x) {
    float r;
    asm("ex2.approx.f32 %0, %1;" : "=f"(r) : "f"(x));
    return r;
}

// ============================================================
// Kernel 1: fused QKV projection (1x1 convs) — unchanged (≈5µs)
// ============================================================
__global__ __launch_bounds__(256) void qkv_kernel(
    const float* __restrict__ x,
    const float* __restrict__ Wq, const float* __restrict__ bq,
    const float* __restrict__ Wk, const float* __restrict__ bk,
    const float* __restrict__ Wv, const float* __restrict__ bv)
{
    __shared__ float x_s[CDIM][65];
    __shared__ float w_s[80 * 64];
    __shared__ float b_s[80];

    const int b  = blockIdx.y;
    const int i0 = blockIdx.x * 64;
    const int tid = threadIdx.x;

    for (int idx = tid; idx < 8 * 64; idx += 256)  w_s[idx]        = Wq[idx];
    for (int idx = tid; idx < 8 * 64; idx += 256)  w_s[512 + idx]  = Wk[idx];
    for (int idx = tid; idx < 64 * 64; idx += 256) w_s[1024 + idx] = Wv[idx];
    if (tid < 8)       b_s[tid] = bq[tid];
    else if (tid < 16) b_s[tid] = bk[tid - 8];
    else if (tid < 80) b_s[tid] = bv[tid - 16];

    for (int idx = tid; idx < 64 * 64; idx += 256) {
        int c = idx >> 6, p = idx & 63;
        x_s[c][p] = x[(b * CDIM + c) * N_PIX + i0 + p];
    }
    __syncthreads();

    const int og = tid >> 6;
    const int p  = tid & 63;

    float acc[20];
#pragma unroll
    for (int k = 0; k < 20; k++) acc[k] = b_s[og * 20 + k];

#pragma unroll 8
    for (int c = 0; c < 64; c++) {
        float xv = x_s[c][p];
#pragma unroll
        for (int k = 0; k < 20; k++)
            acc[k] += w_s[(og * 20 + k) * 64 + c] * xv;
    }

#pragma unroll
    for (int k = 0; k < 20; k++) {
        int o = og * 20 + k;
        float val = acc[k];
        if (o < 8)       g_q[(b * CQKD + o) * N_PIX + i0 + p]        = val;
        else if (o < 16) g_k[(b * CQKD + (o - 8)) * N_PIX + i0 + p]  = val;
        else             g_v[(b * CDIM + (o - 16)) * N_PIX + i0 + p] = val;
    }
}

// ============================================================
// Kernel 2: flash attention + residual, 128 threads, 4q x 8c tiles
//   ty = tid>>3 (0..15) -> q0 = ty*4  (4 queries)
//   tx = tid&7  (0..7)  -> c0 = tx*8  (8 channels) / j-block = tx*8 (8 keys)
// ============================================================
__global__ __launch_bounds__(128, 4) void attn_kernel(
    const float* __restrict__ x,
    const float* __restrict__ gamma,
    float* __restrict__ out)
{
    __shared__ __align__(16) float q_s[CQKD][TQ];    // [d][q], pre-scaled by LOG2E
    __shared__ __align__(16) float k_s[CQKD][TK];    // [d][j]
    __shared__ __align__(16) float v_s[TK][CDIM];    // [j][c]
    __shared__ __align__(16) float p_s[TK][TQ];      // [j][q], XOR-swizzled cols

    const int b   = blockIdx.y;
    const int i0  = blockIdx.x * TQ;
    const int tid = threadIdx.x;
    const int ty  = tid >> 3;     // 0..15
    const int tx  = tid & 7;      // 0..7
    const int q0  = ty * 4;
    const int c0  = tx * 8;

    // load + pre-scale Q tile
#pragma unroll
    for (int r = 0; r < 4; r++) {
        int idx = tid + r * 128;
        int d = idx >> 6, q = idx & 63;
        q_s[d][q] = g_q[(b * CQKD + d) * N_PIX + i0 + q] * LOG2E;
    }

    float m[4], l[4];
    unsigned long long acc[4][4];   // [qq][channel-pair]: (c0+2cp, c0+2cp+1)
#pragma unroll
    for (int qq = 0; qq < 4; qq++) {
        m[qq] = -1e30f; l[qq] = 0.f;
#pragma unroll
        for (int cp = 0; cp < 4; cp++) acc[qq][cp] = 0ull;
    }

    for (int t = 0; t < N_PIX / TK; t++) {
        const int j0g = t * TK;
        __syncthreads();   // prior PV done with k_s/v_s/p_s

        // K tile: k_s[d][j]
#pragma unroll
        for (int r = 0; r < 4; r++) {
            int idx = tid + r * 128;
            int d = idx >> 6, j = idx & 63;
            k_s[d][j] = g_k[(b * CQKD + d) * N_PIX + j0g + j];
        }
        // V tile transposed: v_s[j][c]
#pragma unroll
        for (int r = 0; r < 8; r++) {
            int idx = tid + r * 128;
            int c = idx >> 4, u = idx & 15;
            float4 vv = *reinterpret_cast<const float4*>(
                &g_v[(b * CDIM + c) * N_PIX + j0g + u * 4]);
            v_s[u * 4 + 0][c] = vv.x;
            v_s[u * 4 + 1][c] = vv.y;
            v_s[u * 4 + 2][c] = vv.z;
            v_s[u * 4 + 3][c] = vv.w;
        }
        __syncthreads();

        // ---- scores (f32x2): s2[qq][jp] = pairs over j = tx*8 + 2jp,+1 ----
        unsigned long long s2[4][4];
#pragma unroll
        for (int qq = 0; qq < 4; qq++)
#pragma unroll
            for (int jp = 0; jp < 4; jp++) s2[qq][jp] = 0ull;

#pragma unroll
        for (int d = 0; d < CQKD; d++) {
            ulonglong2 kv0 = *reinterpret_cast<const ulonglong2*>(&k_s[d][tx * 8]);
            ulonglong2 kv1 = *reinterpret_cast<const ulonglong2*>(&k_s[d][tx * 8 + 4]);
            float4 qv = *reinterpret_cast<const float4*>(&q_s[d][q0]);
            unsigned long long pq0 = packf2(qv.x, qv.x);
            unsigned long long pq1 = packf2(qv.y, qv.y);
            unsigned long long pq2 = packf2(qv.z, qv.z);
            unsigned long long pq3 = packf2(qv.w, qv.w);
            s2[0][0] = ffma2(pq0, kv0.x, s2[0][0]);
            s2[0][1] = ffma2(pq0, kv0.y, s2[0][1]);
            s2[0][2] = ffma2(pq0, kv1.x, s2[0][2]);
            s2[0][3] = ffma2(pq0, kv1.y, s2[0][3]);
            s2[1][0] = ffma2(pq1, kv0.x, s2[1][0]);
            s2[1][1] = ffma2(pq1, kv0.y, s2[1][1]);
            s2[1][2] = ffma2(pq1, kv1.x, s2[1][2]);
            s2[1][3] = ffma2(pq1, kv1.y, s2[1][3]);
            s2[2][0] = ffma2(pq2, kv0.x, s2[2][0]);
            s2[2][1] = ffma2(pq2, kv0.y, s2[2][1]);
            s2[2][2] = ffma2(pq2, kv1.x, s2[2][2]);
            s2[2][3] = ffma2(pq2, kv1.y, s2[2][3]);
            s2[3][0] = ffma2(pq3, kv0.x, s2[3][0]);
            s2[3][1] = ffma2(pq3, kv0.y, s2[3][1]);
            s2[3][2] = ffma2(pq3, kv1.x, s2[3][2]);
            s2[3][3] = ffma2(pq3, kv1.y, s2[3][3]);
        }

        // ---- online softmax: reductions over the 8 tx lanes ----
        float p[4][8];
#pragma unroll
        for (int qq = 0; qq < 4; qq++) {
#pragma unroll
            for (int jp = 0; jp < 4; jp++) {
                float2 sp = unpackf2(s2[qq][jp]);
                p[qq][2 * jp]     = sp.x;
                p[qq][2 * jp + 1] = sp.y;
            }
            float tmax = p[qq][0];
#pragma unroll
            for (int jj = 1; jj < 8; jj++) tmax = fmaxf(tmax, p[qq][jj]);
#pragma unroll
            for (int msk = 1; msk < 8; msk <<= 1)
                tmax = fmaxf(tmax, __shfl_xor_sync(0xffffffffu, tmax, msk));
            float mnew = fmaxf(m[qq], tmax);
            float sc   = ex2(m[qq] - mnew);
            m[qq] = mnew;
            float rs = 0.f;
#pragma unroll
            for (int jj = 0; jj < 8; jj++) {
                p[qq][jj] = ex2(p[qq][jj] - mnew);
                rs += p[qq][jj];
            }
#pragma unroll
            for (int msk = 1; msk < 8; msk <<= 1)
                rs += __shfl_xor_sync(0xffffffffu, rs, msk);
            l[qq] = l[qq] * sc + rs;
            unsigned long long sc2 = packf2(sc, sc);
#pragma unroll
            for (int cp = 0; cp < 4; cp++)
                acc[qq][cp] = fmul2(acc[qq][cp], sc2);
        }

        // store P transposed: p_s[row=tx*8+jj][q0..q0+3], swizzled (STS.128)
#pragma unroll
        for (int jj = 0; jj < 8; jj++) {
            int row = tx * 8 + jj;
            float4 pv = make_float4(p[0][jj], p[1][jj], p[2][jj], p[3][jj]);
            *reinterpret_cast<float4*>(&p_s[row][PSWZ(row, q0)]) = pv;
        }
        __syncthreads();

        // ---- PV: acc[qq][cp] += p_s[j][q0+qq] * v_s[j][c0 .. c0+7] ----
#pragma unroll 4
        for (int j = 0; j < TK; j++) {
            float4 pv = *reinterpret_cast<const float4*>(&p_s[j][PSWZ(j, q0)]);
            ulonglong2 v0 = *reinterpret_cast<const ulonglong2*>(&v_s[j][c0]);
            ulonglong2 v1 = *reinterpret_cast<const ulonglong2*>(&v_s[j][c0 + 4]);
            unsigned long long pb0 = packf2(pv.x, pv.x);
            unsigned long long pb1 = packf2(pv.y, pv.y);
            unsigned long long pb2 = packf2(pv.z, pv.z);
            unsigned long long pb3 = packf2(pv.w, pv.w);
            acc[0][0] = ffma2(pb0, v0.x, acc[0][0]);
            acc[0][1] = ffma2(pb0, v0.y, acc[0][1]);
            acc[0][2] = ffma2(pb0, v1.x, acc[0][2]);
            acc[0][3] = ffma2(pb0, v1.y, acc[0][3]);
            acc[1][0] = ffma2(pb1, v0.x, acc[1][0]);
            acc[1][1] = ffma2(pb1, v0.y, acc[1][1]);
            acc[1][2] = ffma2(pb1, v1.x, acc[1][2]);
            acc[1][3] = ffma2(pb1, v1.y, acc[1][3]);
            acc[2][0] = ffma2(pb2, v0.x, acc[2][0]);
            acc[2][1] = ffma2(pb2, v0.y, acc[2][1]);
            acc[2][2] = ffma2(pb2, v1.x, acc[2][2]);
            acc[2][3] = ffma2(pb2, v1.y, acc[2][3]);
            acc[3][0] = ffma2(pb3, v0.x, acc[3][0]);
            acc[3][1] = ffma2(pb3, v0.y, acc[3][1]);
            acc[3][2] = ffma2(pb3, v1.x, acc[3][2]);
            acc[3][3] = ffma2(pb3, v1.y, acc[3][3]);
        }
    }

    // ---- epilogue: normalize + gamma*out + x, straight from registers ----
    const float g = gamma[0];
    float af[4][8];
#pragma unroll
    for (int qq = 0; qq < 4; qq++) {
        float il = 1.0f / l[qq];
#pragma unroll
        for (int cp = 0; cp < 4; cp++) {
            float2 a = unpackf2(acc[qq][cp]);
            af[qq][2 * cp]     = a.x * il;
            af[qq][2 * cp + 1] = a.y * il;
        }
    }
#pragma unroll
    for (int cc = 0; cc < 8; cc++) {
        int gaddr = (b * CDIM + c0 + cc) * N_PIX + i0 + q0;
        float4 xv = *reinterpret_cast<const float4*>(&x[gaddr]);
        float4 ov;
        ov.x = g * af[0][cc] + xv.x;
        ov.y = g * af[1][cc] + xv.y;
        ov.z = g * af[2][cc] + xv.z;
        ov.w = g * af[3][cc] + xv.w;
        *reinterpret_cast<float4*>(&out[gaddr]) = ov;
    }
}

extern "C" void kernel_launch(void* const* d_in, const int* in_sizes, int n_in,
                              void* d_out, int out_size)
{
    const float* x     = (const float*)d_in[0];
    const float* Wq    = (const float*)d_in[1];
    const float* bq    = (const float*)d_in[2];
    const float* Wk    = (const float*)d_in[3];
    const float* bk    = (const float*)d_in[4];
    const float* Wv    = (const float*)d_in[5];
    const float* bv    = (const float*)d_in[6];
    const float* gamma = (const float*)d_in[7];
    float* out = (float*)d_out;

    qkv_kernel<<<dim3(64, BATCH), 256>>>(x, Wq, bq, Wk, bk, Wv, bv);
    attn_kernel<<<dim3(N_PIX / TQ, BATCH), 128>>>(x, gamma, out);
}

// round 4
// speedup vs baseline: 1.6468x; 1.6468x over previous
#include <cuda_runtime.h>
#include <cstdint>

#define N_PIX 4096
#define BATCH 4
#define CDIM  64
#define CQKD  8
#define TQ    64
#define TK    64
#define VSTR  68   // v_s / p_s row stride: 16B-aligned, row adds 4j to bank
#define LOG2E 1.4426950408889634f

// Scratch (device globals: no allocation allowed)
// g_v is stored TRANSPOSED: [b][pix][c]
__device__ float g_q[BATCH * CQKD * N_PIX];
__device__ float g_k[BATCH * CQKD * N_PIX];
__device__ float g_v[BATCH * N_PIX * CDIM];

// ---------- packed f32x2 helpers (Blackwell) ----------
__device__ __forceinline__ unsigned long long ffma2(unsigned long long a,
                                                    unsigned long long b,
                                                    unsigned long long c) {
    unsigned long long d;
    asm("fma.rn.f32x2 %0, %1, %2, %3;" : "=l"(d) : "l"(a), "l"(b), "l"(c));
    return d;
}
__device__ __forceinline__ unsigned long long fmul2(unsigned long long a,
                                                    unsigned long long b) {
    unsigned long long d;
    asm("mul.rn.f32x2 %0, %1, %2;" : "=l"(d) : "l"(a), "l"(b));
    return d;
}
__device__ __forceinline__ unsigned long long packf2(float lo, float hi) {
    unsigned long long r;
    asm("mov.b64 %0, {%1, %2};" : "=l"(r) : "f"(lo), "f"(hi));
    return r;
}
__device__ __forceinline__ float2 unpackf2(unsigned long long v) {
    float lo, hi;
    asm("mov.b64 {%0, %1}, %2;" : "=f"(lo), "=f"(hi) : "l"(v));
    return make_float2(lo, hi);
}
__device__ __forceinline__ float ex2(float x) {
    float r;
    asm("ex2.approx.f32 %0, %1;" : "=f"(r) : "f"(x));
    return r;
}

// ============================================================
// Kernel 1: fused QKV projection. q,k stored [b][d][pix];
// v stored TRANSPOSED [b][pix][c] via padded smem staging.
// ============================================================
__global__ __launch_bounds__(256) void qkv_kernel(
    const float* __restrict__ x,
    const float* __restrict__ Wq, const float* __restrict__ bq,
    const float* __restrict__ Wk, const float* __restrict__ bk,
    const float* __restrict__ Wv, const float* __restrict__ bv)
{
    __shared__ float sbuf[64 * 68];   // x tile (stride 65), then v^T staging (stride 68)
    __shared__ float w_s[80 * 64];
    __shared__ float b_s[80];

    const int b  = blockIdx.y;
    const int i0 = blockIdx.x * 64;
    const int tid = threadIdx.x;

    for (int idx = tid; idx < 8 * 64; idx += 256)  w_s[idx]        = Wq[idx];
    for (int idx = tid; idx < 8 * 64; idx += 256)  w_s[512 + idx]  = Wk[idx];
    for (int idx = tid; idx < 64 * 64; idx += 256) w_s[1024 + idx] = Wv[idx];
    if (tid < 8)       b_s[tid] = bq[tid];
    else if (tid < 16) b_s[tid] = bk[tid - 8];
    else if (tid < 80) b_s[tid] = bv[tid - 16];

    for (int idx = tid; idx < 64 * 64; idx += 256) {
        int c = idx >> 6, p = idx & 63;
        sbuf[c * 65 + p] = x[(b * CDIM + c) * N_PIX + i0 + p];
    }
    __syncthreads();

    const int og = tid >> 6;   // 0..3
    const int p  = tid & 63;

    float acc[20];
#pragma unroll
    for (int k = 0; k < 20; k++) acc[k] = b_s[og * 20 + k];

#pragma unroll 8
    for (int c = 0; c < 64; c++) {
        float xv = sbuf[c * 65 + p];
#pragma unroll
        for (int k = 0; k < 20; k++)
            acc[k] += w_s[(og * 20 + k) * 64 + c] * xv;
    }
    __syncthreads();   // all x reads done; sbuf now reused as v^T staging

    // q, k direct (coalesced); v -> staging tile [p][c] stride 68
#pragma unroll
    for (int k = 0; k < 20; k++) {
        int o = og * 20 + k;
        float val = acc[k];
        if (o < 8)       g_q[(b * CQKD + o) * N_PIX + i0 + p]       = val;
        else if (o < 16) g_k[(b * CQKD + (o - 8)) * N_PIX + i0 + p] = val;
        else             sbuf[p * VSTR + (o - 16)] = val;
    }
    __syncthreads();

    // coalesced transposed write: g_v[(b*N + i0+pix)*64 + c]
#pragma unroll
    for (int r = 0; r < 4; r++) {
        int idx = tid + r * 256;          // 1024 float4 chunks
        int pix = idx >> 4, c4 = (idx & 15) * 4;
        float4 vv = *reinterpret_cast<const float4*>(&sbuf[pix * VSTR + c4]);
        *reinterpret_cast<float4*>(&g_v[(b * N_PIX + i0 + pix) * CDIM + c4]) = vv;
    }
}

// ============================================================
// Kernel 2: flash attention + residual. 128 threads, 4q x 8c.
//   ty = tid>>3 -> q0 = ty*4
//   tx = tid&7  -> channels {4tx..4tx+3} u {32+4tx..32+4tx+3}
//                  keys     {4tx..4tx+3} u {32+4tx..32+4tx+3}
// ============================================================
__global__ __launch_bounds__(128, 4) void attn_kernel(
    const float* __restrict__ x,
    const float* __restrict__ gamma,
    float* __restrict__ out)
{
    __shared__ __align__(16) float q_s[CQKD][TQ];   // [d][q], pre-scaled by LOG2E
    __shared__ __align__(16) float k_s[CQKD][TK];   // [d][j]
    __shared__ __align__(16) float v_s[TK][VSTR];   // [j][c], stride 68
    __shared__ __align__(16) float p_s[TK][VSTR];   // [j][q], stride 68

    const int b   = blockIdx.y;
    const int i0  = blockIdx.x * TQ;
    const int tid = threadIdx.x;
    const int ty  = tid >> 3;     // 0..15
    const int tx  = tid & 7;      // 0..7
    const int q0  = ty * 4;
    const int c0  = tx * 4;       // low channel/key group; high = c0+32

    // load + pre-scale Q tile
#pragma unroll
    for (int r = 0; r < 4; r++) {
        int idx = tid + r * 128;
        int d = idx >> 6, q = idx & 63;
        q_s[d][q] = g_q[(b * CQKD + d) * N_PIX + i0 + q] * LOG2E;
    }

    float m[4], l[4];
    unsigned long long acc[4][4];   // [qq][pair]: pairs (c0,c0+1),(c0+2,c0+3),(+32...)
#pragma unroll
    for (int qq = 0; qq < 4; qq++) {
        m[qq] = -1e30f; l[qq] = 0.f;
#pragma unroll
        for (int cp = 0; cp < 4; cp++) acc[qq][cp] = 0ull;
    }

    for (int t = 0; t < N_PIX / TK; t++) {
        const int j0g = t * TK;
        __syncthreads();   // prior PV done with k_s/v_s/p_s

        // K tile: k_s[d][j] (conflict-free)
#pragma unroll
        for (int r = 0; r < 4; r++) {
            int idx = tid + r * 128;
            int d = idx >> 6, j = idx & 63;
            k_s[d][j] = g_k[(b * CQKD + d) * N_PIX + j0g + j];
        }
        // V tile: direct float4 copy from transposed g_v (coalesced, no transpose)
#pragma unroll
        for (int r = 0; r < 8; r++) {
            int idx = tid + r * 128;          // 1024 chunks
            int j = idx >> 4, c4 = (idx & 15) * 4;
            float4 vv = *reinterpret_cast<const float4*>(
                &g_v[(b * N_PIX + j0g + j) * CDIM + c4]);
            *reinterpret_cast<float4*>(&v_s[j][c4]) = vv;
        }
        __syncthreads();

        // ---- scores (f32x2): j pairs at {c0, c0+2, 32+c0, 32+c0+2} ----
        unsigned long long s2[4][4];
#pragma unroll
        for (int qq = 0; qq < 4; qq++)
#pragma unroll
            for (int jp = 0; jp < 4; jp++) s2[qq][jp] = 0ull;

#pragma unroll
        for (int d = 0; d < CQKD; d++) {
            ulonglong2 kv0 = *reinterpret_cast<const ulonglong2*>(&k_s[d][c0]);
            ulonglong2 kv1 = *reinterpret_cast<const ulonglong2*>(&k_s[d][c0 + 32]);
            float4 qv = *reinterpret_cast<const float4*>(&q_s[d][q0]);
            unsigned long long pq0 = packf2(qv.x, qv.x);
            unsigned long long pq1 = packf2(qv.y, qv.y);
            unsigned long long pq2 = packf2(qv.z, qv.z);
            unsigned long long pq3 = packf2(qv.w, qv.w);
            s2[0][0] = ffma2(pq0, kv0.x, s2[0][0]);
            s2[0][1] = ffma2(pq0, kv0.y, s2[0][1]);
            s2[0][2] = ffma2(pq0, kv1.x, s2[0][2]);
            s2[0][3] = ffma2(pq0, kv1.y, s2[0][3]);
            s2[1][0] = ffma2(pq1, kv0.x, s2[1][0]);
            s2[1][1] = ffma2(pq1, kv0.y, s2[1][1]);
            s2[1][2] = ffma2(pq1, kv1.x, s2[1][2]);
            s2[1][3] = ffma2(pq1, kv1.y, s2[1][3]);
            s2[2][0] = ffma2(pq2, kv0.x, s2[2][0]);
            s2[2][1] = ffma2(pq2, kv0.y, s2[2][1]);
            s2[2][2] = ffma2(pq2, kv1.x, s2[2][2]);
            s2[2][3] = ffma2(pq2, kv1.y, s2[2][3]);
            s2[3][0] = ffma2(pq3, kv0.x, s2[3][0]);
            s2[3][1] = ffma2(pq3, kv0.y, s2[3][1]);
            s2[3][2] = ffma2(pq3, kv1.x, s2[3][2]);
            s2[3][3] = ffma2(pq3, kv1.y, s2[3][3]);
        }

        // ---- online softmax: reduce over the 8 tx lanes ----
        float p[4][8];   // [qq][0..3] = keys c0..c0+3; [4..7] = keys 32+c0..
#pragma unroll
        for (int qq = 0; qq < 4; qq++) {
#pragma unroll
            for (int jp = 0; jp < 4; jp++) {
                float2 sp = unpackf2(s2[qq][jp]);
                p[qq][2 * jp]     = sp.x;
                p[qq][2 * jp + 1] = sp.y;
            }
            float tmax = p[qq][0];
#pragma unroll
            for (int jj = 1; jj < 8; jj++) tmax = fmaxf(tmax, p[qq][jj]);
#pragma unroll
            for (int msk = 1; msk < 8; msk <<= 1)
                tmax = fmaxf(tmax, __shfl_xor_sync(0xffffffffu, tmax, msk));
            float mnew = fmaxf(m[qq], tmax);
            float sc   = ex2(m[qq] - mnew);
            m[qq] = mnew;
            float rs = 0.f;
#pragma unroll
            for (int jj = 0; jj < 8; jj++) {
                p[qq][jj] = ex2(p[qq][jj] - mnew);
                rs += p[qq][jj];
            }
#pragma unroll
            for (int msk = 1; msk < 8; msk <<= 1)
                rs += __shfl_xor_sync(0xffffffffu, rs, msk);
            l[qq] = l[qq] * sc + rs;
            unsigned long long sc2 = packf2(sc, sc);
#pragma unroll
            for (int cp = 0; cp < 4; cp++)
                acc[qq][cp] = fmul2(acc[qq][cp], sc2);
        }

        // store P transposed: rows c0+jj and 32+c0+jj (STS.128, 4-phase floor)
#pragma unroll
        for (int jj = 0; jj < 4; jj++) {
            float4 pv0 = make_float4(p[0][jj], p[1][jj], p[2][jj], p[3][jj]);
            *reinterpret_cast<float4*>(&p_s[c0 + jj][q0]) = pv0;
            float4 pv1 = make_float4(p[0][jj + 4], p[1][jj + 4], p[2][jj + 4], p[3][jj + 4]);
            *reinterpret_cast<float4*>(&p_s[32 + c0 + jj][q0]) = pv1;
        }
        __syncthreads();

        // ---- PV: acc += p_s[j][q0+qq] * v_s[j][{c0, 32+c0}] (all 1-wf LDS) ----
#pragma unroll 4
        for (int j = 0; j < TK; j++) {
            float4 pv = *reinterpret_cast<const float4*>(&p_s[j][q0]);
            ulonglong2 v0 = *reinterpret_cast<const ulonglong2*>(&v_s[j][c0]);
            ulonglong2 v1 = *reinterpret_cast<const ulonglong2*>(&v_s[j][c0 + 32]);
            unsigned long long pb0 = packf2(pv.x, pv.x);
            unsigned long long pb1 = packf2(pv.y, pv.y);
            unsigned long long pb2 = packf2(pv.z, pv.z);
            unsigned long long pb3 = packf2(pv.w, pv.w);
            acc[0][0] = ffma2(pb0, v0.x, acc[0][0]);
            acc[0][1] = ffma2(pb0, v0.y, acc[0][1]);
            acc[0][2] = ffma2(pb0, v1.x, acc[0][2]);
            acc[0][3] = ffma2(pb0, v1.y, acc[0][3]);
            acc[1][0] = ffma2(pb1, v0.x, acc[1][0]);
            acc[1][1] = ffma2(pb1, v0.y, acc[1][1]);
            acc[1][2] = ffma2(pb1, v1.x, acc[1][2]);
            acc[1][3] = ffma2(pb1, v1.y, acc[1][3]);
            acc[2][0] = ffma2(pb2, v0.x, acc[2][0]);
            acc[2][1] = ffma2(pb2, v0.y, acc[2][1]);
            acc[2][2] = ffma2(pb2, v1.x, acc[2][2]);
            acc[2][3] = ffma2(pb2, v1.y, acc[2][3]);
            acc[3][0] = ffma2(pb3, v0.x, acc[3][0]);
            acc[3][1] = ffma2(pb3, v0.y, acc[3][1]);
            acc[3][2] = ffma2(pb3, v1.x, acc[3][2]);
            acc[3][3] = ffma2(pb3, v1.y, acc[3][3]);
        }
    }

    // ---- epilogue: normalize + gamma*out + x, from registers ----
    const float g = gamma[0];
    float af[4][8];
#pragma unroll
    for (int qq = 0; qq < 4; qq++) {
        float il = 1.0f / l[qq];
#pragma unroll
        for (int cp = 0; cp < 4; cp++) {
            float2 a = unpackf2(acc[qq][cp]);
            af[qq][2 * cp]     = a.x * il;
            af[qq][2 * cp + 1] = a.y * il;
        }
    }
#pragma unroll
    for (int cc = 0; cc < 8; cc++) {
        int ch = (cc < 4) ? (c0 + cc) : (32 + c0 + cc - 4);
        int gaddr = (b * CDIM + ch) * N_PIX + i0 + q0;
        float4 xv = *reinterpret_cast<const float4*>(&x[gaddr]);
        float4 ov;
        ov.x = g * af[0][cc] + xv.x;
        ov.y = g * af[1][cc] + xv.y;
        ov.z = g * af[2][cc] + xv.z;
        ov.w = g * af[3][cc] + xv.w;
        *reinterpret_cast<float4*>(&out[gaddr]) = ov;
    }
}

extern "C" void kernel_launch(void* const* d_in, const int* in_sizes, int n_in,
                              void* d_out, int out_size)
{
    const float* x     = (const float*)d_in[0];
    const float* Wq    = (const float*)d_in[1];
    const float* bq    = (const float*)d_in[2];
    const float* Wk    = (const float*)d_in[3];
    const float* bk    = (const float*)d_in[4];
    const float* Wv    = (const float*)d_in[5];
    const float* bv    = (const float*)d_in[6];
    const float* gamma = (const float*)d_in[7];
    float* out = (float*)d_out;

    qkv_kernel<<<dim3(64, BATCH), 256>>>(x, Wq, bq, Wk, bk, Wv, bv);
    attn_kernel<<<dim3(N_PIX / TQ, BATCH), 128>>>(x, gamma, out);
}

// round 5
// speedup vs baseline: 1.7511x; 1.0634x over previous
#include <cuda_runtime.h>
#include <cstdint>

#define N_PIX 4096
#define BATCH 4
#define CDIM  64
#define CQKD  8
#define TQ    64
#define TK    64
#define NSPLIT 2
#define TILES_PER_SPLIT (N_PIX / TK / NSPLIT)   // 32
#define VSTR  68   // v_s / p_s row stride
#define LOG2E 1.4426950408889634f

// Scratch (device globals: no allocation allowed)
__device__ float g_q[BATCH * CQKD * N_PIX];
__device__ float g_k[BATCH * CQKD * N_PIX];
__device__ float g_v[BATCH * N_PIX * CDIM];            // TRANSPOSED [b][pix][c]
__device__ float g_pacc[NSPLIT * BATCH * CDIM * N_PIX]; // partial acc [s][b][c][pix]
__device__ float g_pm[NSPLIT * BATCH * N_PIX];          // partial max (log2 domain)
__device__ float g_pl[NSPLIT * BATCH * N_PIX];          // partial sum

// ---------- packed f32x2 helpers (Blackwell) ----------
__device__ __forceinline__ unsigned long long ffma2(unsigned long long a,
                                                    unsigned long long b,
                                                    unsigned long long c) {
    unsigned long long d;
    asm("fma.rn.f32x2 %0, %1, %2, %3;" : "=l"(d) : "l"(a), "l"(b), "l"(c));
    return d;
}
__device__ __forceinline__ unsigned long long fmul2(unsigned long long a,
                                                    unsigned long long b) {
    unsigned long long d;
    asm("mul.rn.f32x2 %0, %1, %2;" : "=l"(d) : "l"(a), "l"(b));
    return d;
}
__device__ __forceinline__ unsigned long long packf2(float lo, float hi) {
    unsigned long long r;
    asm("mov.b64 %0, {%1, %2};" : "=l"(r) : "f"(lo), "f"(hi));
    return r;
}
__device__ __forceinline__ float2 unpackf2(unsigned long long v) {
    float lo, hi;
    asm("mov.b64 {%0, %1}, %2;" : "=f"(lo), "=f"(hi) : "l"(v));
    return make_float2(lo, hi);
}
__device__ __forceinline__ float ex2(float x) {
    float r;
    asm("ex2.approx.f32 %0, %1;" : "=f"(r) : "f"(x));
    return r;
}

// ============================================================
// Kernel 1: fused QKV projection (unchanged)
// ============================================================
__global__ __launch_bounds__(256) void qkv_kernel(
    const float* __restrict__ x,
    const float* __restrict__ Wq, const float* __restrict__ bq,
    const float* __restrict__ Wk, const float* __restrict__ bk,
    const float* __restrict__ Wv, const float* __restrict__ bv)
{
    __shared__ float sbuf[64 * 68];
    __shared__ float w_s[80 * 64];
    __shared__ float b_s[80];

    const int b  = blockIdx.y;
    const int i0 = blockIdx.x * 64;
    const int tid = threadIdx.x;

    for (int idx = tid; idx < 8 * 64; idx += 256)  w_s[idx]        = Wq[idx];
    for (int idx = tid; idx < 8 * 64; idx += 256)  w_s[512 + idx]  = Wk[idx];
    for (int idx = tid; idx < 64 * 64; idx += 256) w_s[1024 + idx] = Wv[idx];
    if (tid < 8)       b_s[tid] = bq[tid];
    else if (tid < 16) b_s[tid] = bk[tid - 8];
    else if (tid < 80) b_s[tid] = bv[tid - 16];

    for (int idx = tid; idx < 64 * 64; idx += 256) {
        int c = idx >> 6, p = idx & 63;
        sbuf[c * 65 + p] = x[(b * CDIM + c) * N_PIX + i0 + p];
    }
    __syncthreads();

    const int og = tid >> 6;
    const int p  = tid & 63;

    float acc[20];
#pragma unroll
    for (int k = 0; k < 20; k++) acc[k] = b_s[og * 20 + k];

#pragma unroll 8
    for (int c = 0; c < 64; c++) {
        float xv = sbuf[c * 65 + p];
#pragma unroll
        for (int k = 0; k < 20; k++)
            acc[k] += w_s[(og * 20 + k) * 64 + c] * xv;
    }
    __syncthreads();

#pragma unroll
    for (int k = 0; k < 20; k++) {
        int o = og * 20 + k;
        float val = acc[k];
        if (o < 8)       g_q[(b * CQKD + o) * N_PIX + i0 + p]       = val;
        else if (o < 16) g_k[(b * CQKD + (o - 8)) * N_PIX + i0 + p] = val;
        else             sbuf[p * VSTR + (o - 16)] = val;
    }
    __syncthreads();

#pragma unroll
    for (int r = 0; r < 4; r++) {
        int idx = tid + r * 256;
        int pix = idx >> 4, c4 = (idx & 15) * 4;
        float4 vv = *reinterpret_cast<const float4*>(&sbuf[pix * VSTR + c4]);
        *reinterpret_cast<float4*>(&g_v[(b * N_PIX + i0 + pix) * CDIM + c4]) = vv;
    }
}

// ============================================================
// Kernel 2: flash attention, SPLIT-KV. grid (64, B, 2), 128 thr.
// Each block: one 64-query tile x 32 key-tiles (half the keys).
// Writes unnormalized acc + (m, l) partials.
// ============================================================
__global__ __launch_bounds__(128, 4) void attn_kernel()
{
    __shared__ __align__(16) float q_s[CQKD][TQ];
    __shared__ __align__(16) float k_s[CQKD][TK];
    __shared__ __align__(16) float v_s[TK][VSTR];
    __shared__ __align__(16) float p_s[TK][VSTR];

    const int b   = blockIdx.y;
    const int s   = blockIdx.z;
    const int i0  = blockIdx.x * TQ;
    const int tid = threadIdx.x;
    const int ty  = tid >> 3;
    const int tx  = tid & 7;
    const int q0  = ty * 4;
    const int c0  = tx * 4;

#pragma unroll
    for (int r = 0; r < 4; r++) {
        int idx = tid + r * 128;
        int d = idx >> 6, q = idx & 63;
        q_s[d][q] = g_q[(b * CQKD + d) * N_PIX + i0 + q] * LOG2E;
    }

    float m[4], l[4];
    unsigned long long acc[4][4];
#pragma unroll
    for (int qq = 0; qq < 4; qq++) {
        m[qq] = -1e30f; l[qq] = 0.f;
#pragma unroll
        for (int cp = 0; cp < 4; cp++) acc[qq][cp] = 0ull;
    }

    const int t0 = s * TILES_PER_SPLIT;
    for (int t = t0; t < t0 + TILES_PER_SPLIT; t++) {
        const int j0g = t * TK;
        __syncthreads();

#pragma unroll
        for (int r = 0; r < 4; r++) {
            int idx = tid + r * 128;
            int d = idx >> 6, j = idx & 63;
            k_s[d][j] = g_k[(b * CQKD + d) * N_PIX + j0g + j];
        }
#pragma unroll
        for (int r = 0; r < 8; r++) {
            int idx = tid + r * 128;
            int j = idx >> 4, c4 = (idx & 15) * 4;
            float4 vv = *reinterpret_cast<const float4*>(
                &g_v[(b * N_PIX + j0g + j) * CDIM + c4]);
            *reinterpret_cast<float4*>(&v_s[j][c4]) = vv;
        }
        __syncthreads();

        // scores (f32x2)
        unsigned long long s2[4][4];
#pragma unroll
        for (int qq = 0; qq < 4; qq++)
#pragma unroll
            for (int jp = 0; jp < 4; jp++) s2[qq][jp] = 0ull;

#pragma unroll
        for (int d = 0; d < CQKD; d++) {
            ulonglong2 kv0 = *reinterpret_cast<const ulonglong2*>(&k_s[d][c0]);
            ulonglong2 kv1 = *reinterpret_cast<const ulonglong2*>(&k_s[d][c0 + 32]);
            float4 qv = *reinterpret_cast<const float4*>(&q_s[d][q0]);
            unsigned long long pq0 = packf2(qv.x, qv.x);
            unsigned long long pq1 = packf2(qv.y, qv.y);
            unsigned long long pq2 = packf2(qv.z, qv.z);
            unsigned long long pq3 = packf2(qv.w, qv.w);
            s2[0][0] = ffma2(pq0, kv0.x, s2[0][0]);
            s2[0][1] = ffma2(pq0, kv0.y, s2[0][1]);
            s2[0][2] = ffma2(pq0, kv1.x, s2[0][2]);
            s2[0][3] = ffma2(pq0, kv1.y, s2[0][3]);
            s2[1][0] = ffma2(pq1, kv0.x, s2[1][0]);
            s2[1][1] = ffma2(pq1, kv0.y, s2[1][1]);
            s2[1][2] = ffma2(pq1, kv1.x, s2[1][2]);
            s2[1][3] = ffma2(pq1, kv1.y, s2[1][3]);
            s2[2][0] = ffma2(pq2, kv0.x, s2[2][0]);
            s2[2][1] = ffma2(pq2, kv0.y, s2[2][1]);
            s2[2][2] = ffma2(pq2, kv1.x, s2[2][2]);
            s2[2][3] = ffma2(pq2, kv1.y, s2[2][3]);
            s2[3][0] = ffma2(pq3, kv0.x, s2[3][0]);
            s2[3][1] = ffma2(pq3, kv0.y, s2[3][1]);
            s2[3][2] = ffma2(pq3, kv1.x, s2[3][2]);
            s2[3][3] = ffma2(pq3, kv1.y, s2[3][3]);
        }

        // online softmax over the 8 tx lanes
        float p[4][8];
#pragma unroll
        for (int qq = 0; qq < 4; qq++) {
#pragma unroll
            for (int jp = 0; jp < 4; jp++) {
                float2 sp = unpackf2(s2[qq][jp]);
                p[qq][2 * jp]     = sp.x;
                p[qq][2 * jp + 1] = sp.y;
            }
            float tmax = p[qq][0];
#pragma unroll
            for (int jj = 1; jj < 8; jj++) tmax = fmaxf(tmax, p[qq][jj]);
#pragma unroll
            for (int msk = 1; msk < 8; msk <<= 1)
                tmax = fmaxf(tmax, __shfl_xor_sync(0xffffffffu, tmax, msk));
            float mnew = fmaxf(m[qq], tmax);
            float sc   = ex2(m[qq] - mnew);
            m[qq] = mnew;
            float rs = 0.f;
#pragma unroll
            for (int jj = 0; jj < 8; jj++) {
                p[qq][jj] = ex2(p[qq][jj] - mnew);
                rs += p[qq][jj];
            }
#pragma unroll
            for (int msk = 1; msk < 8; msk <<= 1)
                rs += __shfl_xor_sync(0xffffffffu, rs, msk);
            l[qq] = l[qq] * sc + rs;
            unsigned long long sc2 = packf2(sc, sc);
#pragma unroll
            for (int cp = 0; cp < 4; cp++)
                acc[qq][cp] = fmul2(acc[qq][cp], sc2);
        }

#pragma unroll
        for (int jj = 0; jj < 4; jj++) {
            float4 pv0 = make_float4(p[0][jj], p[1][jj], p[2][jj], p[3][jj]);
            *reinterpret_cast<float4*>(&p_s[c0 + jj][q0]) = pv0;
            float4 pv1 = make_float4(p[0][jj + 4], p[1][jj + 4], p[2][jj + 4], p[3][jj + 4]);
            *reinterpret_cast<float4*>(&p_s[32 + c0 + jj][q0]) = pv1;
        }
        __syncthreads();

#pragma unroll 4
        for (int j = 0; j < TK; j++) {
            float4 pv = *reinterpret_cast<const float4*>(&p_s[j][q0]);
            ulonglong2 v0 = *reinterpret_cast<const ulonglong2*>(&v_s[j][c0]);
            ulonglong2 v1 = *reinterpret_cast<const ulonglong2*>(&v_s[j][c0 + 32]);
            unsigned long long pb0 = packf2(pv.x, pv.x);
            unsigned long long pb1 = packf2(pv.y, pv.y);
            unsigned long long pb2 = packf2(pv.z, pv.z);
            unsigned long long pb3 = packf2(pv.w, pv.w);
            acc[0][0] = ffma2(pb0, v0.x, acc[0][0]);
            acc[0][1] = ffma2(pb0, v0.y, acc[0][1]);
            acc[0][2] = ffma2(pb0, v1.x, acc[0][2]);
            acc[0][3] = ffma2(pb0, v1.y, acc[0][3]);
            acc[1][0] = ffma2(pb1, v0.x, acc[1][0]);
            acc[1][1] = ffma2(pb1, v0.y, acc[1][1]);
            acc[1][2] = ffma2(pb1, v1.x, acc[1][2]);
            acc[1][3] = ffma2(pb1, v1.y, acc[1][3]);
            acc[2][0] = ffma2(pb2, v0.x, acc[2][0]);
            acc[2][1] = ffma2(pb2, v0.y, acc[2][1]);
            acc[2][2] = ffma2(pb2, v1.x, acc[2][2]);
            acc[2][3] = ffma2(pb2, v1.y, acc[2][3]);
            acc[3][0] = ffma2(pb3, v0.x, acc[3][0]);
            acc[3][1] = ffma2(pb3, v0.y, acc[3][1]);
            acc[3][2] = ffma2(pb3, v1.x, acc[3][2]);
            acc[3][3] = ffma2(pb3, v1.y, acc[3][3]);
        }
    }

    // ---- write partials: unnormalized acc + (m, l) ----
    float af[4][8];
#pragma unroll
    for (int qq = 0; qq < 4; qq++) {
#pragma unroll
        for (int cp = 0; cp < 4; cp++) {
            float2 a = unpackf2(acc[qq][cp]);
            af[qq][2 * cp]     = a.x;
            af[qq][2 * cp + 1] = a.y;
        }
    }
#pragma unroll
    for (int cc = 0; cc < 8; cc++) {
        int ch = (cc < 4) ? (c0 + cc) : (32 + c0 + cc - 4);
        int gaddr = ((s * BATCH + b) * CDIM + ch) * N_PIX + i0 + q0;
        float4 ov = make_float4(af[0][cc], af[1][cc], af[2][cc], af[3][cc]);
        *reinterpret_cast<float4*>(&g_pacc[gaddr]) = ov;
    }
    if (tx == 0) {
#pragma unroll
        for (int qq = 0; qq < 4; qq++) {
            int qaddr = (s * BATCH + b) * N_PIX + i0 + q0 + qq;
            g_pm[qaddr] = m[qq];
            g_pl[qaddr] = l[qq];
        }
    }
}

// ============================================================
// Kernel 3: combine splits + gamma*out + x residual
//   one thread per (b, c, 4 pixels)
// ============================================================
__global__ __launch_bounds__(256) void combine_kernel(
    const float* __restrict__ x,
    const float* __restrict__ gamma,
    float* __restrict__ out)
{
    const int idx  = blockIdx.x * 256 + threadIdx.x;   // 0 .. 262143
    const int pix4 = idx & 1023;
    const int c    = (idx >> 10) & 63;
    const int b    = idx >> 16;
    const int pix  = pix4 * 4;

    const int qbase0 = (0 * BATCH + b) * N_PIX + pix;
    const int qbase1 = (1 * BATCH + b) * N_PIX + pix;
    float4 m0 = *reinterpret_cast<const float4*>(&g_pm[qbase0]);
    float4 m1 = *reinterpret_cast<const float4*>(&g_pm[qbase1]);
    float4 l0 = *reinterpret_cast<const float4*>(&g_pl[qbase0]);
    float4 l1 = *reinterpret_cast<const float4*>(&g_pl[qbase1]);

    float w0[4], w1[4], inv[4];
    float mm[4] = {fmaxf(m0.x, m1.x), fmaxf(m0.y, m1.y),
                   fmaxf(m0.z, m1.z), fmaxf(m0.w, m1.w)};
    float m0a[4] = {m0.x, m0.y, m0.z, m0.w};
    float m1a[4] = {m1.x, m1.y, m1.z, m1.w};
    float l0a[4] = {l0.x, l0.y, l0.z, l0.w};
    float l1a[4] = {l1.x, l1.y, l1.z, l1.w};
#pragma unroll
    for (int i = 0; i < 4; i++) {
        w0[i] = ex2(m0a[i] - mm[i]);
        w1[i] = ex2(m1a[i] - mm[i]);
        inv[i] = 1.0f / (l0a[i] * w0[i] + l1a[i] * w1[i]);
    }

    const int abase0 = ((0 * BATCH + b) * CDIM + c) * N_PIX + pix;
    const int abase1 = ((1 * BATCH + b) * CDIM + c) * N_PIX + pix;
    float4 a0 = *reinterpret_cast<const float4*>(&g_pacc[abase0]);
    float4 a1 = *reinterpret_cast<const float4*>(&g_pacc[abase1]);

    const int gaddr = (b * CDIM + c) * N_PIX + pix;
    float4 xv = *reinterpret_cast<const float4*>(&x[gaddr]);
    const float g = gamma[0];

    float4 ov;
    ov.x = g * ((a0.x * w0[0] + a1.x * w1[0]) * inv[0]) + xv.x;
    ov.y = g * ((a0.y * w0[1] + a1.y * w1[1]) * inv[1]) + xv.y;
    ov.z = g * ((a0.z * w0[2] + a1.z * w1[2]) * inv[2]) + xv.z;
    ov.w = g * ((a0.w * w0[3] + a1.w * w1[3]) * inv[3]) + xv.w;
    *reinterpret_cast<float4*>(&out[gaddr]) = ov;
}

extern "C" void kernel_launch(void* const* d_in, const int* in_sizes, int n_in,
                              void* d_out, int out_size)
{
    const float* x     = (const float*)d_in[0];
    const float* Wq    = (const float*)d_in[1];
    const float* bq    = (const float*)d_in[2];
    const float* Wk    = (const float*)d_in[3];
    const float* bk    = (const float*)d_in[4];
    const float* Wv    = (const float*)d_in[5];
    const float* bv    = (const float*)d_in[6];
    const float* gamma = (const float*)d_in[7];
    float* out = (float*)d_out;

    qkv_kernel<<<dim3(64, BATCH), 256>>>(x, Wq, bq, Wk, bk, Wv, bv);
    attn_kernel<<<dim3(N_PIX / TQ, BATCH, NSPLIT), 128>>>();
    combine_kernel<<<(BATCH * CDIM * N_PIX / 4) / 256, 256>>>(x, gamma, out);
}

// round 7
// speedup vs baseline: 1.7528x; 1.0010x over previous
#include <cuda_runtime.h>
#include <cstdint>

#define N_PIX 4096
#define BATCH 4
#define CDIM  64
#define CQKD  8
#define TQ    64
#define TK    64
#define NSPLIT 2
#define TILES_PER_SPLIT (N_PIX / TK / NSPLIT)   // 32
#define VSTR  68   // v_s / p_s row stride
#define LOG2E 1.4426950408889634f

// Scratch (device globals: no allocation allowed)
__device__ float g_q[BATCH * CQKD * N_PIX];
__device__ float g_k[BATCH * CQKD * N_PIX];
__device__ float g_v[BATCH * N_PIX * CDIM];            // TRANSPOSED [b][pix][c]
__device__ float g_pacc[NSPLIT * BATCH * CDIM * N_PIX]; // partial acc [s][b][c][pix]
__device__ float g_pm[NSPLIT * BATCH * N_PIX];          // partial max (log2 domain)
__device__ float g_pl[NSPLIT * BATCH * N_PIX];          // partial sum

// ---------- packed f32x2 helpers (Blackwell) ----------
__device__ __forceinline__ unsigned long long ffma2(unsigned long long a,
                                                    unsigned long long b,
                                                    unsigned long long c) {
    unsigned long long d;
    asm("fma.rn.f32x2 %0, %1, %2, %3;" : "=l"(d) : "l"(a), "l"(b), "l"(c));
    return d;
}
__device__ __forceinline__ unsigned long long fmul2(unsigned long long a,
                                                    unsigned long long b) {
    unsigned long long d;
    asm("mul.rn.f32x2 %0, %1, %2;" : "=l"(d) : "l"(a), "l"(b));
    return d;
}
__device__ __forceinline__ unsigned long long packf2(float lo, float hi) {
    unsigned long long r;
    asm("mov.b64 %0, {%1, %2};" : "=l"(r) : "f"(lo), "f"(hi));
    return r;
}
__device__ __forceinline__ float2 unpackf2(unsigned long long v) {
    float lo, hi;
    asm("mov.b64 {%0, %1}, %2;" : "=f"(lo), "=f"(hi) : "l"(v));
    return make_float2(lo, hi);
}
__device__ __forceinline__ float ex2(float x) {
    float r;
    asm("ex2.approx.f32 %0, %1;" : "=f"(r) : "f"(x));
    return r;
}

// ============================================================
// Kernel 1: fused QKV projection (unchanged)
// ============================================================
__global__ __launch_bounds__(256) void qkv_kernel(
    const float* __restrict__ x,
    const float* __restrict__ Wq, const float* __restrict__ bq,
    const float* __restrict__ Wk, const float* __restrict__ bk,
    const float* __restrict__ Wv, const float* __restrict__ bv)
{
    __shared__ float sbuf[64 * 68];
    __shared__ float w_s[80 * 64];
    __shared__ float b_s[80];

    const int b  = blockIdx.y;
    const int i0 = blockIdx.x * 64;
    const int tid = threadIdx.x;

    for (int idx = tid; idx < 8 * 64; idx += 256)  w_s[idx]        = Wq[idx];
    for (int idx = tid; idx < 8 * 64; idx += 256)  w_s[512 + idx]  = Wk[idx];
    for (int idx = tid; idx < 64 * 64; idx += 256) w_s[1024 + idx] = Wv[idx];
    if (tid < 8)       b_s[tid] = bq[tid];
    else if (tid < 16) b_s[tid] = bk[tid - 8];
    else if (tid < 80) b_s[tid] = bv[tid - 16];

    for (int idx = tid; idx < 64 * 64; idx += 256) {
        int c = idx >> 6, p = idx & 63;
        sbuf[c * 65 + p] = x[(b * CDIM + c) * N_PIX + i0 + p];
    }
    __syncthreads();

    const int og = tid >> 6;
    const int p  = tid & 63;

    float acc[20];
#pragma unroll
    for (int k = 0; k < 20; k++) acc[k] = b_s[og * 20 + k];

#pragma unroll 8
    for (int c = 0; c < 64; c++) {
        float xv = sbuf[c * 65 + p];
#pragma unroll
        for (int k = 0; k < 20; k++)
            acc[k] += w_s[(og * 20 + k) * 64 + c] * xv;
    }
    __syncthreads();

#pragma unroll
    for (int k = 0; k < 20; k++) {
        int o = og * 20 + k;
        float val = acc[k];
        if (o < 8)       g_q[(b * CQKD + o) * N_PIX + i0 + p]       = val;
        else if (o < 16) g_k[(b * CQKD + (o - 8)) * N_PIX + i0 + p] = val;
        else             sbuf[p * VSTR + (o - 16)] = val;
    }
    __syncthreads();

#pragma unroll
    for (int r = 0; r < 4; r++) {
        int idx = tid + r * 256;
        int pix = idx >> 4, c4 = (idx & 15) * 4;
        float4 vv = *reinterpret_cast<const float4*>(&sbuf[pix * VSTR + c4]);
        *reinterpret_cast<float4*>(&g_v[(b * N_PIX + i0 + pix) * CDIM + c4]) = vv;
    }
}

// ============================================================
// Kernel 2: flash attention, SPLIT-KV. grid (64, B, 2), 128 thr.
// Each block: one 64-query tile x 32 key-tiles (half the keys).
// Writes unnormalized acc + (m, l) partials.
// ============================================================
__global__ __launch_bounds__(128, 4) void attn_kernel()
{
    __shared__ __align__(16) float q_s[CQKD][TQ];
    __shared__ __align__(16) float k_s[CQKD][TK];
    __shared__ __align__(16) float v_s[TK][VSTR];
    __shared__ __align__(16) float p_s[TK][VSTR];

    const int b   = blockIdx.y;
    const int s   = blockIdx.z;
    const int i0  = blockIdx.x * TQ;
    const int tid = threadIdx.x;
    const int ty  = tid >> 3;
    const int tx  = tid & 7;
    const int q0  = ty * 4;
    const int c0  = tx * 4;

#pragma unroll
    for (int r = 0; r < 4; r++) {
        int idx = tid + r * 128;
        int d = idx >> 6, q = idx & 63;
        q_s[d][q] = g_q[(b * CQKD + d) * N_PIX + i0 + q] * LOG2E;
    }

    float m[4], l[4];
    unsigned long long acc[4][4];
#pragma unroll
    for (int qq = 0; qq < 4; qq++) {
        m[qq] = -1e30f; l[qq] = 0.f;
#pragma unroll
        for (int cp = 0; cp < 4; cp++) acc[qq][cp] = 0ull;
    }

    const int t0 = s * TILES_PER_SPLIT;
    for (int t = t0; t < t0 + TILES_PER_SPLIT; t++) {
        const int j0g = t * TK;
        __syncthreads();

#pragma unroll
        for (int r = 0; r < 4; r++) {
            int idx = tid + r * 128;
            int d = idx >> 6, j = idx & 63;
            k_s[d][j] = g_k[(b * CQKD + d) * N_PIX + j0g + j];
        }
#pragma unroll
        for (int r = 0; r < 8; r++) {
            int idx = tid + r * 128;
            int j = idx >> 4, c4 = (idx & 15) * 4;
            float4 vv = *reinterpret_cast<const float4*>(
                &g_v[(b * N_PIX + j0g + j) * CDIM + c4]);
            *reinterpret_cast<float4*>(&v_s[j][c4]) = vv;
        }
        __syncthreads();

        // scores (f32x2)
        unsigned long long s2[4][4];
#pragma unroll
        for (int qq = 0; qq < 4; qq++)
#pragma unroll
            for (int jp = 0; jp < 4; jp++) s2[qq][jp] = 0ull;

#pragma unroll
        for (int d = 0; d < CQKD; d++) {
            ulonglong2 kv0 = *reinterpret_cast<const ulonglong2*>(&k_s[d][c0]);
            ulonglong2 kv1 = *reinterpret_cast<const ulonglong2*>(&k_s[d][c0 + 32]);
            float4 qv = *reinterpret_cast<const float4*>(&q_s[d][q0]);
            unsigned long long pq0 = packf2(qv.x, qv.x);
            unsigned long long pq1 = packf2(qv.y, qv.y);
            unsigned long long pq2 = packf2(qv.z, qv.z);
            unsigned long long pq3 = packf2(qv.w, qv.w);
            s2[0][0] = ffma2(pq0, kv0.x, s2[0][0]);
            s2[0][1] = ffma2(pq0, kv0.y, s2[0][1]);
            s2[0][2] = ffma2(pq0, kv1.x, s2[0][2]);
            s2[0][3] = ffma2(pq0, kv1.y, s2[0][3]);
            s2[1][0] = ffma2(pq1, kv0.x, s2[1][0]);
            s2[1][1] = ffma2(pq1, kv0.y, s2[1][1]);
            s2[1][2] = ffma2(pq1, kv1.x, s2[1][2]);
            s2[1][3] = ffma2(pq1, kv1.y, s2[1][3]);
            s2[2][0] = ffma2(pq2, kv0.x, s2[2][0]);
            s2[2][1] = ffma2(pq2, kv0.y, s2[2][1]);
            s2[2][2] = ffma2(pq2, kv1.x, s2[2][2]);
            s2[2][3] = ffma2(pq2, kv1.y, s2[2][3]);
            s2[3][0] = ffma2(pq3, kv0.x, s2[3][0]);
            s2[3][1] = ffma2(pq3, kv0.y, s2[3][1]);
            s2[3][2] = ffma2(pq3, kv1.x, s2[3][2]);
            s2[3][3] = ffma2(pq3, kv1.y, s2[3][3]);
        }

        // online softmax over the 8 tx lanes
        float p[4][8];
#pragma unroll
        for (int qq = 0; qq < 4; qq++) {
#pragma unroll
            for (int jp = 0; jp < 4; jp++) {
                float2 sp = unpackf2(s2[qq][jp]);
                p[qq][2 * jp]     = sp.x;
                p[qq][2 * jp + 1] = sp.y;
            }
            float tmax = p[qq][0];
#pragma unroll
            for (int jj = 1; jj < 8; jj++) tmax = fmaxf(tmax, p[qq][jj]);
#pragma unroll
            for (int msk = 1; msk < 8; msk <<= 1)
                tmax = fmaxf(tmax, __shfl_xor_sync(0xffffffffu, tmax, msk));
            float mnew = fmaxf(m[qq], tmax);
            float sc   = ex2(m[qq] - mnew);
            m[qq] = mnew;
            float rs = 0.f;
#pragma unroll
            for (int jj = 0; jj < 8; jj++) {
                p[qq][jj] = ex2(p[qq][jj] - mnew);
                rs += p[qq][jj];
            }
#pragma unroll
            for (int msk = 1; msk < 8; msk <<= 1)
                rs += __shfl_xor_sync(0xffffffffu, rs, msk);
            l[qq] = l[qq] * sc + rs;
            unsigned long long sc2 = packf2(sc, sc);
#pragma unroll
            for (int cp = 0; cp < 4; cp++)
                acc[qq][cp] = fmul2(acc[qq][cp], sc2);
        }

#pragma unroll
        for (int jj = 0; jj < 4; jj++) {
            float4 pv0 = make_float4(p[0][jj], p[1][jj], p[2][jj], p[3][jj]);
            *reinterpret_cast<float4*>(&p_s[c0 + jj][q0]) = pv0;
            float4 pv1 = make_float4(p[0][jj + 4], p[1][jj + 4], p[2][jj + 4], p[3][jj + 4]);
            *reinterpret_cast<float4*>(&p_s[32 + c0 + jj][q0]) = pv1;
        }
        __syncthreads();

#pragma unroll 4
        for (int j = 0; j < TK; j++) {
            float4 pv = *reinterpret_cast<const float4*>(&p_s[j][q0]);
            ulonglong2 v0 = *reinterpret_cast<const ulonglong2*>(&v_s[j][c0]);
            ulonglong2 v1 = *reinterpret_cast<const ulonglong2*>(&v_s[j][c0 + 32]);
            unsigned long long pb0 = packf2(pv.x, pv.x);
            unsigned long long pb1 = packf2(pv.y, pv.y);
            unsigned long long pb2 = packf2(pv.z, pv.z);
            unsigned long long pb3 = packf2(pv.w, pv.w);
            acc[0][0] = ffma2(pb0, v0.x, acc[0][0]);
            acc[0][1] = ffma2(pb0, v0.y, acc[0][1]);
            acc[0][2] = ffma2(pb0, v1.x, acc[0][2]);
            acc[0][3] = ffma2(pb0, v1.y, acc[0][3]);
            acc[1][0] = ffma2(pb1, v0.x, acc[1][0]);
            acc[1][1] = ffma2(pb1, v0.y, acc[1][1]);
            acc[1][2] = ffma2(pb1, v1.x, acc[1][2]);
            acc[1][3] = ffma2(pb1, v1.y, acc[1][3]);
            acc[2][0] = ffma2(pb2, v0.x, acc[2][0]);
            acc[2][1] = ffma2(pb2, v0.y, acc[2][1]);
            acc[2][2] = ffma2(pb2, v1.x, acc[2][2]);
            acc[2][3] = ffma2(pb2, v1.y, acc[2][3]);
            acc[3][0] = ffma2(pb3, v0.x, acc[3][0]);
            acc[3][1] = ffma2(pb3, v0.y, acc[3][1]);
            acc[3][2] = ffma2(pb3, v1.x, acc[3][2]);
            acc[3][3] = ffma2(pb3, v1.y, acc[3][3]);
        }
    }

    // ---- write partials: unnormalized acc + (m, l) ----
    float af[4][8];
#pragma unroll
    for (int qq = 0; qq < 4; qq++) {
#pragma unroll
        for (int cp = 0; cp < 4; cp++) {
            float2 a = unpackf2(acc[qq][cp]);
            af[qq][2 * cp]     = a.x;
            af[qq][2 * cp + 1] = a.y;
        }
    }
#pragma unroll
    for (int cc = 0; cc < 8; cc++) {
        int ch = (cc < 4) ? (c0 + cc) : (32 + c0 + cc - 4);
        int gaddr = ((s * BATCH + b) * CDIM + ch) * N_PIX + i0 + q0;
        float4 ov = make_float4(af[0][cc], af[1][cc], af[2][cc], af[3][cc]);
        *reinterpret_cast<float4*>(&g_pacc[gaddr]) = ov;
    }
    if (tx == 0) {
#pragma unroll
        for (int qq = 0; qq < 4; qq++) {
            int qaddr = (s * BATCH + b) * N_PIX + i0 + q0 + qq;
            g_pm[qaddr] = m[qq];
            g_pl[qaddr] = l[qq];
        }
    }
}

// ============================================================
// Kernel 3: combine splits + gamma*out + x residual
//   one thread per (b, c, 4 pixels)
// ============================================================
__global__ __launch_bounds__(256) void combine_kernel(
    const float* __restrict__ x,
    const float* __restrict__ gamma,
    float* __restrict__ out)
{
    const int idx  = blockIdx.x * 256 + threadIdx.x;   // 0 .. 262143
    const int pix4 = idx & 1023;
    const int c    = (idx >> 10) & 63;
    const int b    = idx >> 16;
    const int pix  = pix4 * 4;

    const int qbase0 = (0 * BATCH + b) * N_PIX + pix;
    const int qbase1 = (1 * BATCH + b) * N_PIX + pix;
    float4 m0 = *reinterpret_cast<const float4*>(&g_pm[qbase0]);
    float4 m1 = *reinterpret_cast<const float4*>(&g_pm[qbase1]);
    float4 l0 = *reinterpret_cast<const float4*>(&g_pl[qbase0]);
    float4 l1 = *reinterpret_cast<const float4*>(&g_pl[qbase1]);

    float w0[4], w1[4], inv[4];
    float mm[4] = {fmaxf(m0.x, m1.x), fmaxf(m0.y, m1.y),
                   fmaxf(m0.z, m1.z), fmaxf(m0.w, m1.w)};
    float m0a[4] = {m0.x, m0.y, m0.z, m0.w};
    float m1a[4] = {m1.x, m1.y, m1.z, m1.w};
    float l0a[4] = {l0.x, l0.y, l0.z, l0.w};
    float l1a[4] = {l1.x, l1.y, l1.z, l1.w};
#pragma unroll
    for (int i = 0; i < 4; i++) {
        w0[i] = ex2(m0a[i] - mm[i]);
        w1[i] = ex2(m1a[i] - mm[i]);
        inv[i] = 1.0f / (l0a[i] * w0[i] + l1a[i] * w1[i]);
    }

    const int abase0 = ((0 * BATCH + b) * CDIM + c) * N_PIX + pix;
    const int abase1 = ((1 * BATCH + b) * CDIM + c) * N_PIX + pix;
    float4 a0 = *reinterpret_cast<const float4*>(&g_pacc[abase0]);
    float4 a1 = *reinterpret_cast<const float4*>(&g_pacc[abase1]);

    const int gaddr = (b * CDIM + c) * N_PIX + pix;
    float4 xv = *reinterpret_cast<const float4*>(&x[gaddr]);
    const float g = gamma[0];

    float4 ov;
    ov.x = g * ((a0.x * w0[0] + a1.x * w1[0]) * inv[0]) + xv.x;
    ov.y = g * ((a0.y * w0[1] + a1.y * w1[1]) * inv[1]) + xv.y;
    ov.z = g * ((a0.z * w0[2] + a1.z * w1[2]) * inv[2]) + xv.z;
    ov.w = g * ((a0.w * w0[3] + a1.w * w1[3]) * inv[3]) + xv.w;
    *reinterpret_cast<float4*>(&out[gaddr]) = ov;
}

extern "C" void kernel_launch(void* const* d_in, const int* in_sizes, int n_in,
                              void* d_out, int out_size)
{
    const float* x     = (const float*)d_in[0];
    const float* Wq    = (const float*)d_in[1];
    const float* bq    = (const float*)d_in[2];
    const float* Wk    = (const float*)d_in[3];
    const float* bk    = (const float*)d_in[4];
    const float* Wv    = (const float*)d_in[5];
    const float* bv    = (const float*)d_in[6];
    const float* gamma = (const float*)d_in[7];
    float* out = (float*)d_out;

    qkv_kernel<<<dim3(64, BATCH), 256>>>(x, Wq, bq, Wk, bk, Wv, bv);
    attn_kernel<<<dim3(N_PIX / TQ, BATCH, NSPLIT), 128>>>();
    combine_kernel<<<(BATCH * CDIM * N_PIX / 4) / 256, 256>>>(x, gamma, out);
}

// round 12
// speedup vs baseline: 4.7684x; 2.7204x over previous
#include <cuda_runtime.h>
#include <cuda_fp16.h>
#include <cstdint>

#define N_PIX 4096
#define BATCH 4
#define CDIM  64
#define CQKD  8
#define TQ    128                 // queries per block (8 warps x 16)
#define TK    64                  // keys per tile
#define NTILE (N_PIX / TK)        // 64
#define LOG2E 1.4426950408889634f

#define KSTR  20   // k_sm row stride in words  (hi d0-7 at +0, lo at +8, pad 4)
#define VSTR  72   // v_sm row stride in halfs  (64 keys + 8 pad; 144B rows, 16B-aligned)

// Scratch (device globals: no allocation allowed)
__device__ float  g_q[BATCH * N_PIX * CQKD];   // [b][pix][d], scaled by LOG2E
__device__ float  g_k[BATCH * N_PIX * CQKD];   // [b][pix][d]
__device__ __half g_vh[BATCH * CDIM * N_PIX];  // [b][c][pix], fp16

// ---------------- helpers ----------------
__device__ __forceinline__ uint32_t tf32r(float x) {
    uint32_t u;
    asm("cvt.rna.tf32.f32 %0, %1;" : "=r"(u) : "f"(x));
    return u;
}
__device__ __forceinline__ float ex2(float x) {
    float r;
    asm("ex2.approx.f32 %0, %1;" : "=f"(r) : "f"(x));
    return r;
}
__device__ __forceinline__ uint32_t h2pack(float hi, float lo) {
    // result: .lo half = lo arg, .hi half = hi arg
    uint32_t d;
    asm("cvt.rn.f16x2.f32 %0, %1, %2;" : "=r"(d) : "f"(hi), "f"(lo));
    return d;
}
__device__ __forceinline__ void mma_tf32(float* c, const uint32_t* a,
                                         uint32_t b0, uint32_t b1) {
    asm volatile(
        "mma.sync.aligned.m16n8k8.row.col.f32.tf32.tf32.f32 "
        "{%0,%1,%2,%3}, {%4,%5,%6,%7}, {%8,%9}, {%0,%1,%2,%3};"
        : "+f"(c[0]), "+f"(c[1]), "+f"(c[2]), "+f"(c[3])
        : "r"(a[0]), "r"(a[1]), "r"(a[2]), "r"(a[3]), "r"(b0), "r"(b1));
}
__device__ __forceinline__ void mma_f16(float* c, const uint32_t* a,
                                        uint32_t b0, uint32_t b1) {
    asm volatile(
        "mma.sync.aligned.m16n8k16.row.col.f32.f16.f16.f32 "
        "{%0,%1,%2,%3}, {%4,%5,%6,%7}, {%8,%9}, {%0,%1,%2,%3};"
        : "+f"(c[0]), "+f"(c[1]), "+f"(c[2]), "+f"(c[3])
        : "r"(a[0]), "r"(a[1]), "r"(a[2]), "r"(a[3]), "r"(b0), "r"(b1));
}

// ============================================================
// Kernel 1: fused QKV projection.
//   g_q[b][pix][d] = LOG2E * (Wq x + bq)     (fp32)
//   g_k[b][pix][d] =          Wk x + bk      (fp32)
//   g_vh[b][c][pix] = fp16(Wv x + bv)
// ============================================================
__global__ __launch_bounds__(256) void qkv_kernel(
    const float* __restrict__ x,
    const float* __restrict__ Wq, const float* __restrict__ bq,
    const float* __restrict__ Wk, const float* __restrict__ bk,
    const float* __restrict__ Wv, const float* __restrict__ bv)
{
    __shared__ float x_s[64 * 65];
    __shared__ float w_s[80 * 64];
    __shared__ float b_s[80];

    const int b  = blockIdx.y;
    const int i0 = blockIdx.x * 64;
    const int tid = threadIdx.x;

    for (int idx = tid; idx < 8 * 64; idx += 256)  w_s[idx]        = Wq[idx];
    for (int idx = tid; idx < 8 * 64; idx += 256)  w_s[512 + idx]  = Wk[idx];
    for (int idx = tid; idx < 64 * 64; idx += 256) w_s[1024 + idx] = Wv[idx];
    if (tid < 8)       b_s[tid] = bq[tid];
    else if (tid < 16) b_s[tid] = bk[tid - 8];
    else if (tid < 80) b_s[tid] = bv[tid - 16];

    for (int idx = tid; idx < 64 * 64; idx += 256) {
        int c = idx >> 6, p = idx & 63;
        x_s[c * 65 + p] = x[(b * CDIM + c) * N_PIX + i0 + p];
    }
    __syncthreads();

    const int og = tid >> 6;   // 0..3
    const int p  = tid & 63;

    float acc[20];
#pragma unroll
    for (int k = 0; k < 20; k++) acc[k] = b_s[og * 20 + k];

#pragma unroll 8
    for (int c = 0; c < 64; c++) {
        float xv = x_s[c * 65 + p];
#pragma unroll
        for (int k = 0; k < 20; k++)
            acc[k] += w_s[(og * 20 + k) * 64 + c] * xv;
    }

    const int pix = i0 + p;
    if (og == 0) {
        float4 q0 = make_float4(acc[0] * LOG2E, acc[1] * LOG2E,
                                acc[2] * LOG2E, acc[3] * LOG2E);
        float4 q1 = make_float4(acc[4] * LOG2E, acc[5] * LOG2E,
                                acc[6] * LOG2E, acc[7] * LOG2E);
        *reinterpret_cast<float4*>(&g_q[(b * N_PIX + pix) * 8])     = q0;
        *reinterpret_cast<float4*>(&g_q[(b * N_PIX + pix) * 8 + 4]) = q1;
        float4 k0 = make_float4(acc[8], acc[9], acc[10], acc[11]);
        float4 k1 = make_float4(acc[12], acc[13], acc[14], acc[15]);
        *reinterpret_cast<float4*>(&g_k[(b * N_PIX + pix) * 8])     = k0;
        *reinterpret_cast<float4*>(&g_k[(b * N_PIX + pix) * 8 + 4]) = k1;
#pragma unroll
        for (int k = 16; k < 20; k++)
            g_vh[(b * CDIM + (k - 16)) * N_PIX + pix] = __float2half_rn(acc[k]);
    } else {
#pragma unroll
        for (int k = 0; k < 20; k++) {
            int c = og * 20 + k - 16;
            g_vh[(b * CDIM + c) * N_PIX + pix] = __float2half_rn(acc[k]);
        }
    }
}

// ============================================================
// Kernel 2: FlashAttention-2 on mma.sync.
// grid (32, 4), 256 threads (8 warps), warp w -> queries w*16..w*16+15.
// S: m16n8k8 tf32 (3xTF32 compensated). PV: m16n8k16 f16.
// ============================================================
__global__ __launch_bounds__(256) void attn_kernel(
    const float* __restrict__ x,
    const float* __restrict__ gamma,
    float* __restrict__ out)
{
    __shared__ __align__(16) float  k_sm[TK * KSTR];   // [j][20w]: hi d0-7, lo d0-7, pad
    __shared__ __align__(16) __half v_sm[CDIM * VSTR]; // [c][j] stride 72 halfs

    const int b    = blockIdx.y;
    const int i0   = blockIdx.x * TQ;
    const int tid  = threadIdx.x;
    const int wid  = tid >> 5;
    const int lane = tid & 31;
    const int gid  = lane >> 2;     // 0..7
    const int tig  = lane & 3;      // 0..3
    const int qrow = wid * 16 + gid;   // + 0 / + 8 rows

    // ---- Q A-fragments (hi/lo tf32), loaded once ----
    uint32_t a_hi[4], a_lo[4];
    {
        const float* qb = &g_q[(b * N_PIX + i0) * 8];
        float qv[4];
        qv[0] = qb[(qrow)     * 8 + tig];
        qv[1] = qb[(qrow + 8) * 8 + tig];
        qv[2] = qb[(qrow)     * 8 + tig + 4];
        qv[3] = qb[(qrow + 8) * 8 + tig + 4];
#pragma unroll
        for (int i = 0; i < 4; i++) {
            a_hi[i] = tf32r(qv[i]);
            a_lo[i] = tf32r(qv[i] - __uint_as_float(a_hi[i]));
        }
    }

    float m[2] = {-1e30f, -1e30f};
    float l[2] = {0.f, 0.f};
    float o[8][4];
#pragma unroll
    for (int nt = 0; nt < 8; nt++)
#pragma unroll
        for (int e = 0; e < 4; e++) o[nt][e] = 0.f;

    for (int t = 0; t < NTILE; t++) {
        const int j0g = t * TK;
        __syncthreads();

        // ---- fill K (hi/lo tf32): thread -> pix = tid>>2, d pair = 2*(tid&3)
        {
            int pix = tid >> 2, part = tid & 3;
            float2 kv = *reinterpret_cast<const float2*>(
                &g_k[(b * N_PIX + j0g + pix) * 8 + 2 * part]);
            uint32_t h0 = tf32r(kv.x), h1 = tf32r(kv.y);
            uint32_t l0 = tf32r(kv.x - __uint_as_float(h0));
            uint32_t l1 = tf32r(kv.y - __uint_as_float(h1));
            float* row = &k_sm[pix * KSTR];
            *reinterpret_cast<float2*>(&row[2 * part]) =
                make_float2(__uint_as_float(h0), __uint_as_float(h1));
            *reinterpret_cast<float2*>(&row[8 + 2 * part]) =
                make_float2(__uint_as_float(l0), __uint_as_float(l1));
        }
        // ---- fill V fp16: 512 chunks of 8 halfs
#pragma unroll
        for (int r = 0; r < 2; r++) {
            int idx = tid + r * 256;
            int c = idx >> 3, m8 = idx & 7;
            uint4 hv = *reinterpret_cast<const uint4*>(
                &g_vh[(b * CDIM + c) * N_PIX + j0g + m8 * 8]);
            *reinterpret_cast<uint4*>(&v_sm[c * VSTR + m8 * 8]) = hv;
        }
        __syncthreads();

        // ---- S = Q K^T (3xTF32): s[nt] covers j = 8nt + 2tig + {0,1}
        float s[8][4];
#pragma unroll
        for (int nt = 0; nt < 8; nt++)
#pragma unroll
            for (int e = 0; e < 4; e++) s[nt][e] = 0.f;

#pragma unroll
        for (int nt = 0; nt < 8; nt++) {
            const float* kr = &k_sm[(8 * nt + gid) * KSTR];
            uint32_t bh0 = __float_as_uint(kr[tig]);
            uint32_t bh1 = __float_as_uint(kr[tig + 4]);
            uint32_t bl0 = __float_as_uint(kr[8 + tig]);
            uint32_t bl1 = __float_as_uint(kr[12 + tig]);
            mma_tf32(s[nt], a_hi, bh0, bh1);
            mma_tf32(s[nt], a_hi, bl0, bl1);
            mma_tf32(s[nt], a_lo, bh0, bh1);
        }

        // ---- online softmax (rows: qrow [e0,e1], qrow+8 [e2,e3]) ----
        float mx0 = s[0][0], mx1 = s[0][2];
#pragma unroll
        for (int nt = 0; nt < 8; nt++) {
            mx0 = fmaxf(mx0, fmaxf(s[nt][0], s[nt][1]));
            mx1 = fmaxf(mx1, fmaxf(s[nt][2], s[nt][3]));
        }
        mx0 = fmaxf(mx0, __shfl_xor_sync(0xffffffffu, mx0, 1));
        mx0 = fmaxf(mx0, __shfl_xor_sync(0xffffffffu, mx0, 2));
        mx1 = fmaxf(mx1, __shfl_xor_sync(0xffffffffu, mx1, 1));
        mx1 = fmaxf(mx1, __shfl_xor_sync(0xffffffffu, mx1, 2));

        float mn0 = fmaxf(m[0], mx0), mn1 = fmaxf(m[1], mx1);
        float sc0 = ex2(m[0] - mn0),  sc1 = ex2(m[1] - mn1);
        m[0] = mn0; m[1] = mn1;

        float p[8][4];
        float ls0 = 0.f, ls1 = 0.f;
#pragma unroll
        for (int nt = 0; nt < 8; nt++) {
            p[nt][0] = ex2(s[nt][0] - mn0);
            p[nt][1] = ex2(s[nt][1] - mn0);
            p[nt][2] = ex2(s[nt][2] - mn1);
            p[nt][3] = ex2(s[nt][3] - mn1);
            ls0 += p[nt][0] + p[nt][1];
            ls1 += p[nt][2] + p[nt][3];
        }
        ls0 += __shfl_xor_sync(0xffffffffu, ls0, 1);
        ls0 += __shfl_xor_sync(0xffffffffu, ls0, 2);
        ls1 += __shfl_xor_sync(0xffffffffu, ls1, 1);
        ls1 += __shfl_xor_sync(0xffffffffu, ls1, 2);
        l[0] = l[0] * sc0 + ls0;
        l[1] = l[1] * sc1 + ls1;

        // rescale PV accumulators
#pragma unroll
        for (int nt = 0; nt < 8; nt++) {
            o[nt][0] *= sc0; o[nt][1] *= sc0;
            o[nt][2] *= sc1; o[nt][3] *= sc1;
        }

        // ---- PV: P(16x64) fp16 (register A-frags) x V(64x64) fp16 ----
#pragma unroll
        for (int kk = 0; kk < 4; kk++) {
            uint32_t af[4];
            af[0] = h2pack(p[2 * kk][1],     p[2 * kk][0]);
            af[1] = h2pack(p[2 * kk][3],     p[2 * kk][2]);
            af[2] = h2pack(p[2 * kk + 1][1], p[2 * kk + 1][0]);
            af[3] = h2pack(p[2 * kk + 1][3], p[2 * kk + 1][2]);
#pragma unroll
            for (int ntc = 0; ntc < 8; ntc++) {
                int cc = 8 * ntc + gid;
                uint32_t b0 = *reinterpret_cast<const uint32_t*>(
                    &v_sm[cc * VSTR + 16 * kk + 2 * tig]);
                uint32_t b1 = *reinterpret_cast<const uint32_t*>(
                    &v_sm[cc * VSTR + 16 * kk + 2 * tig + 8]);
                mma_f16(o[ntc], af, b0, b1);
            }
        }
    }

    // ---- epilogue: normalize + gamma*out + x ----
    const float inv0 = 1.0f / l[0];
    const float inv1 = 1.0f / l[1];
    const float g = gamma[0];
#pragma unroll
    for (int ntc = 0; ntc < 8; ntc++) {
#pragma unroll
        for (int e = 0; e < 2; e++) {
            int c = 8 * ntc + 2 * tig + e;
            int a0 = (b * CDIM + c) * N_PIX + i0 + qrow;
            out[a0] = g * (o[ntc][e] * inv0) + x[a0];
            int a1 = a0 + 8;
            out[a1] = g * (o[ntc][2 + e] * inv1) + x[a1];
        }
    }
}

extern "C" void kernel_launch(void* const* d_in, const int* in_sizes, int n_in,
                              void* d_out, int out_size)
{
    const float* x     = (const float*)d_in[0];
    const float* Wq    = (const float*)d_in[1];
    const float* bq    = (const float*)d_in[2];
    const float* Wk    = (const float*)d_in[3];
    const float* bk    = (const float*)d_in[4];
    const float* Wv    = (const float*)d_in[5];
    const float* bv    = (const float*)d_in[6];
    const float* gamma = (const float*)d_in[7];
    float* out = (float*)d_out;

    qkv_kernel<<<dim3(64, BATCH), 256>>>(x, Wq, bq, Wk, bk, Wv, bv);
    attn_kernel<<<dim3(N_PIX / TQ, BATCH), 256>>>(x, gamma, out);
}

// round 14
// speedup vs baseline: 6.8688x; 1.4405x over previous
#include <cuda_runtime.h>
#include <cuda_fp16.h>
#include <cstdint>

#define N_PIX 4096
#define BATCH 4
#define CDIM  64
#define CQKD  8
#define TQ    128                 // queries per block (8 warps x 16)
#define TK    64                  // keys per tile
#define NTILE (N_PIX / TK)        // 64
#define NSPLIT 2
#define TPS   (NTILE / NSPLIT)    // 32 tiles per split
#define LOG2E 1.4426950408889634f

#define KSTR  20   // k_sm row stride in words (hi d0-7 at +0, lo at +8, pad 4)
#define VSTR  72   // v_sm row stride in halfs (64 keys + 8 pad)

// Scratch (device globals: no allocation allowed)
__device__ float  g_q[BATCH * N_PIX * CQKD];    // [b][pix][d], scaled by LOG2E
__device__ float  g_k[BATCH * N_PIX * CQKD];    // [b][pix][d]
__device__ __half g_vh[BATCH * CDIM * N_PIX];   // [b][c][pix], fp16
__device__ float  g_pacc[NSPLIT * BATCH * CDIM * N_PIX]; // [s][b][c][pix]
__device__ float  g_pm[NSPLIT * BATCH * N_PIX];
__device__ float  g_pl[NSPLIT * BATCH * N_PIX];

// ---------------- helpers ----------------
__device__ __forceinline__ uint32_t tf32r(float x) {
    uint32_t u;
    asm("cvt.rna.tf32.f32 %0, %1;" : "=r"(u) : "f"(x));
    return u;
}
__device__ __forceinline__ float ex2(float x) {
    float r;
    asm("ex2.approx.f32 %0, %1;" : "=f"(r) : "f"(x));
    return r;
}
__device__ __forceinline__ uint32_t h2pack(float hi, float lo) {
    uint32_t d;
    asm("cvt.rn.f16x2.f32 %0, %1, %2;" : "=r"(d) : "f"(hi), "f"(lo));
    return d;
}
__device__ __forceinline__ void mma_tf32(float* c, const uint32_t* a,
                                         uint32_t b0, uint32_t b1) {
    asm volatile(
        "mma.sync.aligned.m16n8k8.row.col.f32.tf32.tf32.f32 "
        "{%0,%1,%2,%3}, {%4,%5,%6,%7}, {%8,%9}, {%0,%1,%2,%3};"
        : "+f"(c[0]), "+f"(c[1]), "+f"(c[2]), "+f"(c[3])
        : "r"(a[0]), "r"(a[1]), "r"(a[2]), "r"(a[3]), "r"(b0), "r"(b1));
}
__device__ __forceinline__ void mma_f16(float* c, const uint32_t* a,
                                        uint32_t b0, uint32_t b1) {
    asm volatile(
        "mma.sync.aligned.m16n8k16.row.col.f32.f16.f16.f32 "
        "{%0,%1,%2,%3}, {%4,%5,%6,%7}, {%8,%9}, {%0,%1,%2,%3};"
        : "+f"(c[0]), "+f"(c[1]), "+f"(c[2]), "+f"(c[3])
        : "r"(a[0]), "r"(a[1]), "r"(a[2]), "r"(a[3]), "r"(b0), "r"(b1));
}

// ============================================================
// Kernel 1: fused QKV projection (float4-vectorized fills)
// ============================================================
__global__ __launch_bounds__(256) void qkv_kernel(
    const float* __restrict__ x,
    const float* __restrict__ Wq, const float* __restrict__ bq,
    const float* __restrict__ Wk, const float* __restrict__ bk,
    const float* __restrict__ Wv, const float* __restrict__ bv)
{
    __shared__ float x_s[64 * 68];
    __shared__ float w_s[80 * 64];
    __shared__ float b_s[80];

    const int b  = blockIdx.y;
    const int i0 = blockIdx.x * 64;
    const int tid = threadIdx.x;

    // weights: 1280 float4 chunks (Wq 0..127, Wk 128..255, Wv 256..1279)
    for (int idx = tid; idx < 1280; idx += 256) {
        float4 w;
        if (idx < 128)      w = reinterpret_cast<const float4*>(Wq)[idx];
        else if (idx < 256) w = reinterpret_cast<const float4*>(Wk)[idx - 128];
        else                w = reinterpret_cast<const float4*>(Wv)[idx - 256];
        reinterpret_cast<float4*>(w_s)[idx] = w;
    }
    if (tid < 8)       b_s[tid] = bq[tid];
    else if (tid < 16) b_s[tid] = bk[tid - 8];
    else if (tid < 80) b_s[tid] = bv[tid - 16];

    for (int idx = tid; idx < 1024; idx += 256) {
        int c = idx >> 4, p4 = (idx & 15) * 4;
        float4 xv = *reinterpret_cast<const float4*>(
            &x[(b * CDIM + c) * N_PIX + i0 + p4]);
        *reinterpret_cast<float4*>(&x_s[c * 68 + p4]) = xv;
    }
    __syncthreads();

    const int og = tid >> 6;   // 0..3
    const int p  = tid & 63;

    float acc[20];
#pragma unroll
    for (int k = 0; k < 20; k++) acc[k] = b_s[og * 20 + k];

#pragma unroll 8
    for (int c = 0; c < 64; c++) {
        float xv = x_s[c * 68 + p];
#pragma unroll
        for (int k = 0; k < 20; k++)
            acc[k] += w_s[(og * 20 + k) * 64 + c] * xv;
    }

    const int pix = i0 + p;
    if (og == 0) {
        float4 q0 = make_float4(acc[0] * LOG2E, acc[1] * LOG2E,
                                acc[2] * LOG2E, acc[3] * LOG2E);
        float4 q1 = make_float4(acc[4] * LOG2E, acc[5] * LOG2E,
                                acc[6] * LOG2E, acc[7] * LOG2E);
        *reinterpret_cast<float4*>(&g_q[(b * N_PIX + pix) * 8])     = q0;
        *reinterpret_cast<float4*>(&g_q[(b * N_PIX + pix) * 8 + 4]) = q1;
        float4 k0 = make_float4(acc[8], acc[9], acc[10], acc[11]);
        float4 k1 = make_float4(acc[12], acc[13], acc[14], acc[15]);
        *reinterpret_cast<float4*>(&g_k[(b * N_PIX + pix) * 8])     = k0;
        *reinterpret_cast<float4*>(&g_k[(b * N_PIX + pix) * 8 + 4]) = k1;
#pragma unroll
        for (int k = 16; k < 20; k++)
            g_vh[(b * CDIM + (k - 16)) * N_PIX + pix] = __float2half_rn(acc[k]);
    } else {
#pragma unroll
        for (int k = 0; k < 20; k++) {
            int c = og * 20 + k - 16;
            g_vh[(b * CDIM + c) * N_PIX + pix] = __float2half_rn(acc[k]);
        }
    }
}

// ============================================================
// Kernel 2: FlashAttention-2 on mma.sync, SPLIT-KV x2,
// double-buffered smem with register prefetch.
// grid (32, 4, 2), 256 threads (8 warps).
// ============================================================
__global__ __launch_bounds__(256, 2) void attn_kernel()
{
    __shared__ __align__(16) float  k_sm[2][TK * KSTR];
    __shared__ __align__(16) __half v_sm[2][CDIM * VSTR];

    const int b    = blockIdx.y;
    const int s    = blockIdx.z;
    const int i0   = blockIdx.x * TQ;
    const int tid  = threadIdx.x;
    const int wid  = tid >> 5;
    const int lane = tid & 31;
    const int gid  = lane >> 2;
    const int tig  = lane & 3;
    const int qrow = wid * 16 + gid;

    // per-thread fill coordinates
    const int kpix  = tid >> 2, kpart = tid & 3;
    const int vc0 = tid >> 3,        vm0 = tid & 7;
    const int vc1 = (tid + 256) >> 3, vm1 = (tid + 256) & 7;

    // ---- Q A-fragments (hi/lo tf32), loaded once ----
    uint32_t a_hi[4], a_lo[4];
    {
        const float* qb = &g_q[(b * N_PIX + i0) * 8];
        float qv[4];
        qv[0] = qb[(qrow)     * 8 + tig];
        qv[1] = qb[(qrow + 8) * 8 + tig];
        qv[2] = qb[(qrow)     * 8 + tig + 4];
        qv[3] = qb[(qrow + 8) * 8 + tig + 4];
#pragma unroll
        for (int i = 0; i < 4; i++) {
            a_hi[i] = tf32r(qv[i]);
            a_lo[i] = tf32r(qv[i] - __uint_as_float(a_hi[i]));
        }
    }

    float m[2] = {-1e30f, -1e30f};
    float l[2] = {0.f, 0.f};
    float o[8][4];
#pragma unroll
    for (int nt = 0; nt < 8; nt++)
#pragma unroll
        for (int e = 0; e < 4; e++) o[nt][e] = 0.f;

    const int t0 = s * TPS, t1 = t0 + TPS;

    // ---- prologue: fill buffer 0 with tile t0 ----
    {
        const int jg = t0 * TK;
        float2 pk = *reinterpret_cast<const float2*>(
            &g_k[(b * N_PIX + jg + kpix) * 8 + 2 * kpart]);
        uint4 pv0 = *reinterpret_cast<const uint4*>(
            &g_vh[(b * CDIM + vc0) * N_PIX + jg + vm0 * 8]);
        uint4 pv1 = *reinterpret_cast<const uint4*>(
            &g_vh[(b * CDIM + vc1) * N_PIX + jg + vm1 * 8]);
        uint32_t h0 = tf32r(pk.x), h1 = tf32r(pk.y);
        uint32_t lo0 = tf32r(pk.x - __uint_as_float(h0));
        uint32_t lo1 = tf32r(pk.y - __uint_as_float(h1));
        float* row = &k_sm[0][kpix * KSTR];
        *reinterpret_cast<float2*>(&row[2 * kpart]) =
            make_float2(__uint_as_float(h0), __uint_as_float(h1));
        *reinterpret_cast<float2*>(&row[8 + 2 * kpart]) =
            make_float2(__uint_as_float(lo0), __uint_as_float(lo1));
        *reinterpret_cast<uint4*>(&v_sm[0][vc0 * VSTR + vm0 * 8]) = pv0;
        *reinterpret_cast<uint4*>(&v_sm[0][vc1 * VSTR + vm1 * 8]) = pv1;
        __syncthreads();
    }

    for (int t = t0; t < t1; t++) {
        const int buf = (t - t0) & 1;
        // ---- prefetch tile t+1 into registers (clamped on last) ----
        const int tn = (t + 1 < t1) ? t + 1 : t;
        const int jn = tn * TK;
        float2 pk = *reinterpret_cast<const float2*>(
            &g_k[(b * N_PIX + jn + kpix) * 8 + 2 * kpart]);
        uint4 pv0 = *reinterpret_cast<const uint4*>(
            &g_vh[(b * CDIM + vc0) * N_PIX + jn + vm0 * 8]);
        uint4 pv1 = *reinterpret_cast<const uint4*>(
            &g_vh[(b * CDIM + vc1) * N_PIX + jn + vm1 * 8]);

        // ---- S = Q K^T (3xTF32) ----
        float sreg[8][4];
#pragma unroll
        for (int nt = 0; nt < 8; nt++)
#pragma unroll
            for (int e = 0; e < 4; e++) sreg[nt][e] = 0.f;

#pragma unroll
        for (int nt = 0; nt < 8; nt++) {
            const float* kr = &k_sm[buf][(8 * nt + gid) * KSTR];
            uint32_t bh0 = __float_as_uint(kr[tig]);
            uint32_t bh1 = __float_as_uint(kr[tig + 4]);
            uint32_t bl0 = __float_as_uint(kr[8 + tig]);
            uint32_t bl1 = __float_as_uint(kr[12 + tig]);
            mma_tf32(sreg[nt], a_hi, bh0, bh1);
            mma_tf32(sreg[nt], a_hi, bl0, bl1);
            mma_tf32(sreg[nt], a_lo, bh0, bh1);
        }

        // ---- online softmax ----
        float mx0 = sreg[0][0], mx1 = sreg[0][2];
#pragma unroll
        for (int nt = 0; nt < 8; nt++) {
            mx0 = fmaxf(mx0, fmaxf(sreg[nt][0], sreg[nt][1]));
            mx1 = fmaxf(mx1, fmaxf(sreg[nt][2], sreg[nt][3]));
        }
        mx0 = fmaxf(mx0, __shfl_xor_sync(0xffffffffu, mx0, 1));
        mx0 = fmaxf(mx0, __shfl_xor_sync(0xffffffffu, mx0, 2));
        mx1 = fmaxf(mx1, __shfl_xor_sync(0xffffffffu, mx1, 1));
        mx1 = fmaxf(mx1, __shfl_xor_sync(0xffffffffu, mx1, 2));

        float mn0 = fmaxf(m[0], mx0), mn1 = fmaxf(m[1], mx1);
        float sc0 = ex2(m[0] - mn0),  sc1 = ex2(m[1] - mn1);
        m[0] = mn0; m[1] = mn1;

        float p[8][4];
        float ls0 = 0.f, ls1 = 0.f;
#pragma unroll
        for (int nt = 0; nt < 8; nt++) {
            p[nt][0] = ex2(sreg[nt][0] - mn0);
            p[nt][1] = ex2(sreg[nt][1] - mn0);
            p[nt][2] = ex2(sreg[nt][2] - mn1);
            p[nt][3] = ex2(sreg[nt][3] - mn1);
            ls0 += p[nt][0] + p[nt][1];
            ls1 += p[nt][2] + p[nt][3];
        }
        ls0 += __shfl_xor_sync(0xffffffffu, ls0, 1);
        ls0 += __shfl_xor_sync(0xffffffffu, ls0, 2);
        ls1 += __shfl_xor_sync(0xffffffffu, ls1, 1);
        ls1 += __shfl_xor_sync(0xffffffffu, ls1, 2);
        l[0] = l[0] * sc0 + ls0;
        l[1] = l[1] * sc1 + ls1;

#pragma unroll
        for (int nt = 0; nt < 8; nt++) {
            o[nt][0] *= sc0; o[nt][1] *= sc0;
            o[nt][2] *= sc1; o[nt][3] *= sc1;
        }

        // ---- PV: fp16 mma ----
#pragma unroll
        for (int kk = 0; kk < 4; kk++) {
            uint32_t af[4];
            af[0] = h2pack(p[2 * kk][1],     p[2 * kk][0]);
            af[1] = h2pack(p[2 * kk][3],     p[2 * kk][2]);
            af[2] = h2pack(p[2 * kk + 1][1], p[2 * kk + 1][0]);
            af[3] = h2pack(p[2 * kk + 1][3], p[2 * kk + 1][2]);
#pragma unroll
            for (int ntc = 0; ntc < 8; ntc++) {
                int cc = 8 * ntc + gid;
                uint32_t b0 = *reinterpret_cast<const uint32_t*>(
                    &v_sm[buf][cc * VSTR + 16 * kk + 2 * tig]);
                uint32_t b1 = *reinterpret_cast<const uint32_t*>(
                    &v_sm[buf][cc * VSTR + 16 * kk + 2 * tig + 8]);
                mma_f16(o[ntc], af, b0, b1);
            }
        }

        // ---- store prefetched tile into other buffer ----
        {
            uint32_t h0 = tf32r(pk.x), h1 = tf32r(pk.y);
            uint32_t lo0 = tf32r(pk.x - __uint_as_float(h0));
            uint32_t lo1 = tf32r(pk.y - __uint_as_float(h1));
            float* row = &k_sm[buf ^ 1][kpix * KSTR];
            *reinterpret_cast<float2*>(&row[2 * kpart]) =
                make_float2(__uint_as_float(h0), __uint_as_float(h1));
            *reinterpret_cast<float2*>(&row[8 + 2 * kpart]) =
                make_float2(__uint_as_float(lo0), __uint_as_float(lo1));
            *reinterpret_cast<uint4*>(&v_sm[buf ^ 1][vc0 * VSTR + vm0 * 8]) = pv0;
            *reinterpret_cast<uint4*>(&v_sm[buf ^ 1][vc1 * VSTR + vm1 * 8]) = pv1;
        }
        __syncthreads();
    }

    // ---- write partials: unnormalized o + (m, l) ----
#pragma unroll
    for (int ntc = 0; ntc < 8; ntc++) {
#pragma unroll
        for (int e = 0; e < 2; e++) {
            int c = 8 * ntc + 2 * tig + e;
            int a0 = ((s * BATCH + b) * CDIM + c) * N_PIX + i0 + qrow;
            g_pacc[a0]     = o[ntc][e];
            g_pacc[a0 + 8] = o[ntc][2 + e];
        }
    }
    if (tig == 0) {
        int qa = (s * BATCH + b) * N_PIX + i0 + qrow;
        g_pm[qa]     = m[0];
        g_pm[qa + 8] = m[1];
        g_pl[qa]     = l[0];
        g_pl[qa + 8] = l[1];
    }
}

// ============================================================
// Kernel 3: combine splits + gamma*out + x residual
// ============================================================
__global__ __launch_bounds__(256) void combine_kernel(
    const float* __restrict__ x,
    const float* __restrict__ gamma,
    float* __restrict__ out)
{
    const int idx  = blockIdx.x * 256 + threadIdx.x;
    const int pix4 = idx & 1023;
    const int c    = (idx >> 10) & 63;
    const int b    = idx >> 16;
    const int pix  = pix4 * 4;

    const int qbase0 = (0 * BATCH + b) * N_PIX + pix;
    const int qbase1 = (1 * BATCH + b) * N_PIX + pix;
    float4 m0 = *reinterpret_cast<const float4*>(&g_pm[qbase0]);
    float4 m1 = *reinterpret_cast<const float4*>(&g_pm[qbase1]);
    float4 l0 = *reinterpret_cast<const float4*>(&g_pl[qbase0]);
    float4 l1 = *reinterpret_cast<const float4*>(&g_pl[qbase1]);

    float w0[4], w1[4], inv[4];
    float mm[4] = {fmaxf(m0.x, m1.x), fmaxf(m0.y, m1.y),
                   fmaxf(m0.z, m1.z), fmaxf(m0.w, m1.w)};
    float m0a[4] = {m0.x, m0.y, m0.z, m0.w};
    float m1a[4] = {m1.x, m1.y, m1.z, m1.w};
    float l0a[4] = {l0.x, l0.y, l0.z, l0.w};
    float l1a[4] = {l1.x, l1.y, l1.z, l1.w};
#pragma unroll
    for (int i = 0; i < 4; i++) {
        w0[i] = ex2(m0a[i] - mm[i]);
        w1[i] = ex2(m1a[i] - mm[i]);
        inv[i] = 1.0f / (l0a[i] * w0[i] + l1a[i] * w1[i]);
    }

    const int abase0 = ((0 * BATCH + b) * CDIM + c) * N_PIX + pix;
    const int abase1 = ((1 * BATCH + b) * CDIM + c) * N_PIX + pix;
    float4 a0 = *reinterpret_cast<const float4*>(&g_pacc[abase0]);
    float4 a1 = *reinterpret_cast<const float4*>(&g_pacc[abase1]);

    const int gaddr = (b * CDIM + c) * N_PIX + pix;
    float4 xv = *reinterpret_cast<const float4*>(&x[gaddr]);
    const float g = gamma[0];

    float4 ov;
    ov.x = g * ((a0.x * w0[0] + a1.x * w1[0]) * inv[0]) + xv.x;
    ov.y = g * ((a0.y * w0[1] + a1.y * w1[1]) * inv[1]) + xv.y;
    ov.z = g * ((a0.z * w0[2] + a1.z * w1[2]) * inv[2]) + xv.z;
    ov.w = g * ((a0.w * w0[3] + a1.w * w1[3]) * inv[3]) + xv.w;
    *reinterpret_cast<float4*>(&out[gaddr]) = ov;
}

extern "C" void kernel_launch(void* const* d_in, const int* in_sizes, int n_in,
                              void* d_out, int out_size)
{
    const float* x     = (const float*)d_in[0];
    const float* Wq    = (const float*)d_in[1];
    const float* bq    = (const float*)d_in[2];
    const float* Wk    = (const float*)d_in[3];
    const float* bk    = (const float*)d_in[4];
    const float* Wv    = (const float*)d_in[5];
    const float* bv    = (const float*)d_in[6];
    const float* gamma = (const float*)d_in[7];
    float* out = (float*)d_out;

    qkv_kernel<<<dim3(64, BATCH), 256>>>(x, Wq, bq, Wk, bk, Wv, bv);
    attn_kernel<<<dim3(N_PIX / TQ, BATCH, NSPLIT), 256>>>();
    combine_kernel<<<(BATCH * CDIM * N_PIX / 4) / 256, 256>>>(x, gamma, out);
}